// round 2
// baseline (speedup 1.0000x reference)
#include <cuda_runtime.h>

// Problem constants
#define T_SEQ 2048
#define C_DIM 1024
#define H_DIM 64
#define B_DIM 16
#define M_ROWS (B_DIM * T_SEQ)   // 32768

// Scratch for Q/K/V projections (static device allocation — no cudaMalloc)
__device__ float g_q[M_ROWS * H_DIM];
__device__ float g_k[M_ROWS * H_DIM];
__device__ float g_v[M_ROWS * H_DIM];

// ---------------------------------------------------------------------------
// Projection GEMM: out[m][h] = sum_k x[m][k] * w[k][h]
// M = 32768, K = 1024, N = 64.  Tile: BM=64, BN=64(full H), BK=16.
// 256 threads, each computes a 4x4 micro-tile.
// blockIdx.y selects which of {w_q, w_k, w_v} / {g_q, g_k, g_v}.
// ---------------------------------------------------------------------------
__global__ __launch_bounds__(256) void proj_kernel(
    const float* __restrict__ x,
    const float* __restrict__ wq,
    const float* __restrict__ wk,
    const float* __restrict__ wv)
{
    __shared__ float As[64][16];   // x tile   [m][k]
    __shared__ float Bs[16][64];   // w tile   [k][h]

    const float* w;
    float* outp;
    if (blockIdx.y == 0)      { w = wq; outp = g_q; }
    else if (blockIdx.y == 1) { w = wk; outp = g_k; }
    else                      { w = wv; outp = g_v; }

    const int m0  = blockIdx.x * 64;
    const int tid = threadIdx.x;
    const int tx  = tid & 15;        // h-group (4 cols)
    const int ty  = tid >> 4;        // m-group (4 rows)
    const int arow = tid >> 2;       // 0..63  (A load row)
    const int ac4  = tid & 3;        // 0..3   (A load f4 chunk)

    float acc[4][4] = {};

    for (int k0 = 0; k0 < C_DIM; k0 += 16) {
        float4 av = *(const float4*)(x + (size_t)(m0 + arow) * C_DIM + k0 + ac4 * 4);
        float4 bv = *(const float4*)(w + (size_t)(k0 + ty) * H_DIM + tx * 4);
        *(float4*)&As[arow][ac4 * 4] = av;
        *(float4*)&Bs[ty][tx * 4]    = bv;
        __syncthreads();

        #pragma unroll
        for (int k4 = 0; k4 < 4; k4++) {
            float4 a[4];
            float4 bjv[4];
            #pragma unroll
            for (int i = 0; i < 4; i++) a[i]   = *(float4*)&As[ty * 4 + i][k4 * 4];
            #pragma unroll
            for (int j = 0; j < 4; j++) bjv[j] = *(float4*)&Bs[k4 * 4 + j][tx * 4];
            #pragma unroll
            for (int i = 0; i < 4; i++) {
                const float* ai = &a[i].x;
                #pragma unroll
                for (int j = 0; j < 4; j++) {
                    float s = ai[j];
                    acc[i][0] += s * bjv[j].x;
                    acc[i][1] += s * bjv[j].y;
                    acc[i][2] += s * bjv[j].z;
                    acc[i][3] += s * bjv[j].w;
                }
            }
        }
        __syncthreads();
    }

    #pragma unroll
    for (int i = 0; i < 4; i++) {
        float4 v = make_float4(acc[i][0], acc[i][1], acc[i][2], acc[i][3]);
        *(float4*)(outp + (size_t)(m0 + ty * 4 + i) * H_DIM + tx * 4) = v;
    }
}

// ---------------------------------------------------------------------------
// Flash attention (causal), fp32, online softmax.
// Block: 256 threads, BQ = 64 queries, key tiles of 64.
// Score phase:  warp w owns rows 8w..8w+7; lane owns key cols {lane, lane+32}.
//               K tile smem uses XOR chunk swizzle (kk+c)&15 -> conflict-free
//               float4 loads with stride-64 rows.
// PV phase:     thread (ty,tx) owns a 4x4 (rows, h) micro-tile. P loads are
//               broadcasts, V loads dedup to 256B/warp.
// Grid: x = 32 q-tiles (reversed => heavy tiles first), y = 16 batches.
// Dynamic smem: Qs/Ks/Vs/Ps 64x64 each + per-row stats = 66304 bytes.
// ---------------------------------------------------------------------------
__global__ __launch_bounds__(256, 3) void attn_kernel(float* __restrict__ out)
{
    extern __shared__ float sm[];
    float* Qs   = sm;           // [64][64]
    float* Ks   = sm + 4096;    // [64][64] swizzled chunks
    float* Vs   = sm + 8192;    // [64][64]
    float* Ps   = sm + 12288;   // [64][64]
    float* m_s  = sm + 16384;   // [64] running max
    float* l_s  = m_s + 64;     // [64] running denom
    float* al_s = l_s + 64;     // [64] rescale factor this tile

    const int b    = blockIdx.y;
    const int qt   = gridDim.x - 1 - blockIdx.x;   // heavy tiles first
    const int q0   = qt * 64;
    const int tid  = threadIdx.x;
    const int warp = tid >> 5;
    const int lane = tid & 31;
    const int tx   = tid & 15;   // PV: h group
    const int ty   = tid >> 4;   // PV: row group

    const float* qb = g_q + (size_t)b * T_SEQ * H_DIM;
    const float* kb = g_k + (size_t)b * T_SEQ * H_DIM;
    const float* vb = g_v + (size_t)b * T_SEQ * H_DIM;

    // Load Q tile (coalesced, plain layout)
    #pragma unroll
    for (int rep = 0; rep < 4; rep++) {
        int f  = tid + rep * 256;
        int r  = f >> 4;
        int kk = f & 15;
        *(float4*)&Qs[r * 64 + kk * 4] =
            *(const float4*)&qb[(size_t)(q0 + r) * H_DIM + kk * 4];
    }
    if (tid < 64) { m_s[tid] = -1e30f; l_s[tid] = 0.0f; }

    float o[4][4] = {};
    const int c0 = lane;
    const int c1 = lane + 32;

    __syncthreads();

    for (int j0 = 0; j0 <= q0; j0 += 64) {
        // ---- Load K (swizzled) and V (plain) tiles ----
        #pragma unroll
        for (int rep = 0; rep < 4; rep++) {
            int f  = tid + rep * 256;
            int c  = f >> 4;
            int kk = f & 15;
            float4 kv = *(const float4*)&kb[(size_t)(j0 + c) * H_DIM + kk * 4];
            float4 vv = *(const float4*)&vb[(size_t)(j0 + c) * H_DIM + kk * 4];
            *(float4*)&Ks[c * 64 + (((kk + c) & 15) << 2)] = kv;
            *(float4*)&Vs[c * 64 + kk * 4]                 = vv;
        }
        __syncthreads();

        // ---- Scores + online softmax ----
        #pragma unroll 2
        for (int i = 0; i < 8; i++) {
            const int r = warp * 8 + i;
            float s0 = 0.0f, s1 = 0.0f;
            #pragma unroll
            for (int kk = 0; kk < 16; kk++) {
                float4 q4 = *(float4*)&Qs[r * 64 + kk * 4];
                float4 ka = *(float4*)&Ks[c0 * 64 + (((kk + c0) & 15) << 2)];
                float4 kc = *(float4*)&Ks[c1 * 64 + (((kk + c1) & 15) << 2)];
                s0 += q4.x * ka.x; s0 += q4.y * ka.y;
                s0 += q4.z * ka.z; s0 += q4.w * ka.w;
                s1 += q4.x * kc.x; s1 += q4.y * kc.y;
                s1 += q4.z * kc.z; s1 += q4.w * kc.w;
            }
            s0 *= 0.125f;  // H^-0.5 = 1/8
            s1 *= 0.125f;
            if (j0 + c0 > q0 + r) s0 = -1e30f;  // causal mask
            if (j0 + c1 > q0 + r) s1 = -1e30f;

            float mt = fmaxf(s0, s1);
            #pragma unroll
            for (int off = 16; off > 0; off >>= 1)
                mt = fmaxf(mt, __shfl_xor_sync(0xffffffffu, mt, off));

            float m_old = m_s[r];               // read precedes lane0 write below
            float m_new = fmaxf(m_old, mt);
            float p0 = __expf(s0 - m_new);
            float p1 = __expf(s1 - m_new);
            float rs = p0 + p1;
            #pragma unroll
            for (int off = 16; off > 0; off >>= 1)
                rs += __shfl_xor_sync(0xffffffffu, rs, off);

            if (lane == 0) {
                float alpha = __expf(m_old - m_new);  // m_old=-1e30 -> alpha=0
                l_s[r]  = l_s[r] * alpha + rs;
                m_s[r]  = m_new;
                al_s[r] = alpha;
            }
            Ps[r * 64 + c0] = p0;
            Ps[r * 64 + c1] = p1;
        }
        __syncthreads();

        // ---- O = O*alpha + P @ V  (4x4 register micro-tile) ----
        {
            float al[4];
            #pragma unroll
            for (int i = 0; i < 4; i++) al[i] = al_s[ty * 4 + i];
            #pragma unroll
            for (int i = 0; i < 4; i++) {
                o[i][0] *= al[i]; o[i][1] *= al[i];
                o[i][2] *= al[i]; o[i][3] *= al[i];
            }
            #pragma unroll
            for (int j4 = 0; j4 < 16; j4++) {
                float4 p4[4];
                #pragma unroll
                for (int i = 0; i < 4; i++)
                    p4[i] = *(float4*)&Ps[(ty * 4 + i) * 64 + j4 * 4];
                #pragma unroll
                for (int jj = 0; jj < 4; jj++) {
                    float4 v4 = *(float4*)&Vs[(j4 * 4 + jj) * 64 + tx * 4];
                    #pragma unroll
                    for (int i = 0; i < 4; i++) {
                        float p = (&p4[i].x)[jj];
                        o[i][0] += p * v4.x;
                        o[i][1] += p * v4.y;
                        o[i][2] += p * v4.z;
                        o[i][3] += p * v4.w;
                    }
                }
            }
        }
        __syncthreads();  // protect Ks/Vs/Ps before next tile's loads
    }

    // ---- Finalize: divide by l, write out ----
    #pragma unroll
    for (int i = 0; i < 4; i++) {
        float inv = 1.0f / l_s[ty * 4 + i];
        float4 v = make_float4(o[i][0] * inv, o[i][1] * inv,
                               o[i][2] * inv, o[i][3] * inv);
        *(float4*)(out + ((size_t)b * T_SEQ + q0 + ty * 4 + i) * H_DIM + tx * 4) = v;
    }
}

// ---------------------------------------------------------------------------
extern "C" void kernel_launch(void* const* d_in, const int* in_sizes, int n_in,
                              void* d_out, int out_size)
{
    const float* x  = (const float*)d_in[0];
    const float* wq = (const float*)d_in[1];
    const float* wk = (const float*)d_in[2];
    const float* wv = (const float*)d_in[3];
    float* out = (float*)d_out;

    (void)in_sizes; (void)n_in; (void)out_size;

    // 66304 B dynamic smem > 48KB static limit -> opt in (host attr set; not a
    // stream op, not an allocation; safe under graph capture).
    static const size_t kAttnSmem = (4 * 64 * 64 + 3 * 64) * sizeof(float);
    cudaFuncSetAttribute(attn_kernel,
                         cudaFuncAttributeMaxDynamicSharedMemorySize,
                         (int)kAttnSmem);

    // QKV projection: grid (M/64 = 512, 3 matrices)
    proj_kernel<<<dim3(M_ROWS / 64, 3), 256>>>(x, wq, wk, wv);

    // Attention: grid (32 q-tiles, 16 batches)
    attn_kernel<<<dim3(T_SEQ / 64, B_DIM), 256, kAttnSmem>>>(out);
}

// round 3
// speedup vs baseline: 1.8964x; 1.8964x over previous
#include <cuda_runtime.h>

// Problem constants
#define T_SEQ 2048
#define C_DIM 1024
#define H_DIM 64
#define B_DIM 16
#define M_ROWS (B_DIM * T_SEQ)   // 32768

// Scratch for Q/K/V projections (static device allocation — no cudaMalloc)
__device__ float g_q[M_ROWS * H_DIM];
__device__ float g_k[M_ROWS * H_DIM];
__device__ float g_v[M_ROWS * H_DIM];

// ---------------------------------------------------------------------------
// Projection GEMM: out[m][h] = sum_k x[m][k] * w[k][h]
// M = 32768, K = 1024, N = 64.  Tile: BM=64, BN=64(full H), BK=16.
// 256 threads, 4x4 micro-tile each. Software prefetch of the next k-tile
// (LDG issued right after the barrier, consumed after compute) so global
// latency overlaps FFMA work instead of stalling every CTA in lockstep.
// ---------------------------------------------------------------------------
__global__ __launch_bounds__(256) void proj_kernel(
    const float* __restrict__ x,
    const float* __restrict__ wq,
    const float* __restrict__ wk,
    const float* __restrict__ wv)
{
    __shared__ float As[64][16];   // x tile   [m][k]
    __shared__ float Bs[16][64];   // w tile   [k][h]

    const float* w;
    float* outp;
    if (blockIdx.y == 0)      { w = wq; outp = g_q; }
    else if (blockIdx.y == 1) { w = wk; outp = g_k; }
    else                      { w = wv; outp = g_v; }

    const int m0  = blockIdx.x * 64;
    const int tid = threadIdx.x;
    const int tx  = tid & 15;        // h-group (4 cols)
    const int ty  = tid >> 4;        // m-group (4 rows)
    const int arow = tid >> 2;       // 0..63  (A load row)
    const int ac4  = tid & 3;        // 0..3   (A load f4 chunk)

    float acc[4][4] = {};

    // Prefetch first tile
    float4 av = *(const float4*)(x + (size_t)(m0 + arow) * C_DIM + ac4 * 4);
    float4 bv = *(const float4*)(w + (size_t)ty * H_DIM + tx * 4);

    for (int k0 = 0; k0 < C_DIM; k0 += 16) {
        *(float4*)&As[arow][ac4 * 4] = av;
        *(float4*)&Bs[ty][tx * 4]    = bv;
        __syncthreads();

        // Issue next tile's loads now; they retire during compute below.
        if (k0 + 16 < C_DIM) {
            av = *(const float4*)(x + (size_t)(m0 + arow) * C_DIM + (k0 + 16) + ac4 * 4);
            bv = *(const float4*)(w + (size_t)(k0 + 16 + ty) * H_DIM + tx * 4);
        }

        #pragma unroll
        for (int k4 = 0; k4 < 4; k4++) {
            float4 a[4];
            float4 bjv[4];
            #pragma unroll
            for (int i = 0; i < 4; i++) a[i]   = *(float4*)&As[ty * 4 + i][k4 * 4];
            #pragma unroll
            for (int j = 0; j < 4; j++) bjv[j] = *(float4*)&Bs[k4 * 4 + j][tx * 4];
            #pragma unroll
            for (int i = 0; i < 4; i++) {
                const float* ai = &a[i].x;
                #pragma unroll
                for (int j = 0; j < 4; j++) {
                    float s = ai[j];
                    acc[i][0] += s * bjv[j].x;
                    acc[i][1] += s * bjv[j].y;
                    acc[i][2] += s * bjv[j].z;
                    acc[i][3] += s * bjv[j].w;
                }
            }
        }
        __syncthreads();
    }

    #pragma unroll
    for (int i = 0; i < 4; i++) {
        float4 v = make_float4(acc[i][0], acc[i][1], acc[i][2], acc[i][3]);
        *(float4*)(outp + (size_t)(m0 + ty * 4 + i) * H_DIM + tx * 4) = v;
    }
}

// ---------------------------------------------------------------------------
// Flash attention (causal), fp32, online softmax.
// Block: 256 threads, BQ = 64 queries, key tiles of 64.
//
// Both score and PV phases are 4x4 register-tiled GEMMs: thread (ty,tx) owns
// score rows ty*4..+3 x key-cols tx*4..+3, and O rows ty*4..+3 x h-cols
// tx*4..+3. The 16-thread ty-group persistently owns its 4 q-rows, so the
// online-softmax stats (m, l, alpha) live entirely in registers, reduced
// with 16-lane shfl_xor. K tile is stored with chunk' = kk ^ (row>>2) XOR
// swizzle: score-phase reads step rows by 4, so row>>2 spreads the 16 rows
// read per warp across all 16 chunk positions (2-cyc crossbar floor).
// Scale (1/8) is folded into the Qs load. Causal mask only on diag tile.
// Grid: x = 32 q-tiles (reversed => heavy tiles first), y = 16 batches.
// Dynamic smem: Qs/Ks/Vs/Ps 64x64 = 65536 bytes.
// ---------------------------------------------------------------------------
__global__ __launch_bounds__(256, 2) void attn_kernel(float* __restrict__ out)
{
    extern __shared__ float sm[];
    float* Qs = sm;           // [64][64] pre-scaled by 0.125
    float* Ks = sm + 4096;    // [64][64] XOR-swizzled chunks
    float* Vs = sm + 8192;    // [64][64] plain
    float* Ps = sm + 12288;   // [64][64]

    const int b    = blockIdx.y;
    const int qt   = gridDim.x - 1 - blockIdx.x;   // heavy tiles first
    const int q0   = qt * 64;
    const int tid  = threadIdx.x;
    const int tx   = tid & 15;   // col group
    const int ty   = tid >> 4;   // row group

    const float* qb = g_q + (size_t)b * T_SEQ * H_DIM;
    const float* kb = g_k + (size_t)b * T_SEQ * H_DIM;
    const float* vb = g_v + (size_t)b * T_SEQ * H_DIM;

    // Load Q tile (coalesced), folding in the 1/sqrt(H) = 0.125 scale.
    #pragma unroll
    for (int rep = 0; rep < 4; rep++) {
        int f  = tid + rep * 256;
        int r  = f >> 4;
        int kk = f & 15;
        float4 q = *(const float4*)&qb[(size_t)(q0 + r) * H_DIM + kk * 4];
        q.x *= 0.125f; q.y *= 0.125f; q.z *= 0.125f; q.w *= 0.125f;
        *(float4*)&Qs[r * 64 + kk * 4] = q;
    }

    float o[4][4] = {};
    float m_r[4], l_r[4];
    #pragma unroll
    for (int i = 0; i < 4; i++) { m_r[i] = -1e30f; l_r[i] = 0.0f; }

    __syncthreads();

    for (int j0 = 0; j0 <= q0; j0 += 64) {
        // ---- Load K (swizzled) and V (plain) tiles ----
        #pragma unroll
        for (int rep = 0; rep < 4; rep++) {
            int f  = tid + rep * 256;
            int c  = f >> 4;
            int kk = f & 15;
            float4 kv = *(const float4*)&kb[(size_t)(j0 + c) * H_DIM + kk * 4];
            float4 vv = *(const float4*)&vb[(size_t)(j0 + c) * H_DIM + kk * 4];
            *(float4*)&Ks[c * 64 + (((kk ^ (c >> 2)) & 15) << 2)] = kv;
            *(float4*)&Vs[c * 64 + kk * 4]                        = vv;
        }
        __syncthreads();

        // ---- Scores: S = Q @ K^T, 4x4 register micro-tile ----
        float s[4][4] = {};
        #pragma unroll
        for (int h4 = 0; h4 < 16; h4++) {
            float4 q4[4], k4[4];
            #pragma unroll
            for (int i = 0; i < 4; i++)
                q4[i] = *(float4*)&Qs[(ty * 4 + i) * 64 + h4 * 4];
            #pragma unroll
            for (int j = 0; j < 4; j++) {
                int r = tx * 4 + j;
                k4[j] = *(float4*)&Ks[r * 64 + (((h4 ^ (r >> 2)) & 15) << 2)];
            }
            #pragma unroll
            for (int i = 0; i < 4; i++) {
                #pragma unroll
                for (int j = 0; j < 4; j++) {
                    s[i][j] += q4[i].x * k4[j].x;
                    s[i][j] += q4[i].y * k4[j].y;
                    s[i][j] += q4[i].z * k4[j].z;
                    s[i][j] += q4[i].w * k4[j].w;
                }
            }
        }

        // Causal mask: only the diagonal tile has masked entries.
        if (j0 == q0) {
            #pragma unroll
            for (int i = 0; i < 4; i++)
                #pragma unroll
                for (int j = 0; j < 4; j++)
                    if (tx * 4 + j > ty * 4 + i) s[i][j] = -1e30f;
        }

        // ---- Online softmax, stats in registers ----
        float mt[4], rs[4], alpha[4];
        #pragma unroll
        for (int i = 0; i < 4; i++)
            mt[i] = fmaxf(fmaxf(s[i][0], s[i][1]), fmaxf(s[i][2], s[i][3]));
        #pragma unroll
        for (int off = 8; off > 0; off >>= 1) {
            #pragma unroll
            for (int i = 0; i < 4; i++)
                mt[i] = fmaxf(mt[i], __shfl_xor_sync(0xffffffffu, mt[i], off));
        }
        #pragma unroll
        for (int i = 0; i < 4; i++) {
            float m_new = fmaxf(m_r[i], mt[i]);
            alpha[i] = __expf(m_r[i] - m_new);   // m_r=-1e30 -> alpha=0
            m_r[i]   = m_new;
            s[i][0] = __expf(s[i][0] - m_new);
            s[i][1] = __expf(s[i][1] - m_new);
            s[i][2] = __expf(s[i][2] - m_new);
            s[i][3] = __expf(s[i][3] - m_new);
            rs[i] = (s[i][0] + s[i][1]) + (s[i][2] + s[i][3]);
        }
        #pragma unroll
        for (int off = 8; off > 0; off >>= 1) {
            #pragma unroll
            for (int i = 0; i < 4; i++)
                rs[i] += __shfl_xor_sync(0xffffffffu, rs[i], off);
        }
        #pragma unroll
        for (int i = 0; i < 4; i++) {
            l_r[i] = l_r[i] * alpha[i] + rs[i];
            // Rescale O accumulator
            o[i][0] *= alpha[i]; o[i][1] *= alpha[i];
            o[i][2] *= alpha[i]; o[i][3] *= alpha[i];
            // Publish P row chunk
            *(float4*)&Ps[(ty * 4 + i) * 64 + tx * 4] =
                make_float4(s[i][0], s[i][1], s[i][2], s[i][3]);
        }
        __syncthreads();

        // ---- O += P @ V  (4x4 register micro-tile) ----
        #pragma unroll
        for (int j4 = 0; j4 < 16; j4++) {
            float4 p4[4];
            #pragma unroll
            for (int i = 0; i < 4; i++)
                p4[i] = *(float4*)&Ps[(ty * 4 + i) * 64 + j4 * 4];
            #pragma unroll
            for (int jj = 0; jj < 4; jj++) {
                float4 v4 = *(float4*)&Vs[(j4 * 4 + jj) * 64 + tx * 4];
                #pragma unroll
                for (int i = 0; i < 4; i++) {
                    float p = (&p4[i].x)[jj];
                    o[i][0] += p * v4.x;
                    o[i][1] += p * v4.y;
                    o[i][2] += p * v4.z;
                    o[i][3] += p * v4.w;
                }
            }
        }
        __syncthreads();  // protect Ks/Vs/Ps before next tile's loads
    }

    // ---- Finalize: divide by l, write out ----
    #pragma unroll
    for (int i = 0; i < 4; i++) {
        float inv = 1.0f / l_r[i];
        float4 v = make_float4(o[i][0] * inv, o[i][1] * inv,
                               o[i][2] * inv, o[i][3] * inv);
        *(float4*)(out + ((size_t)b * T_SEQ + q0 + ty * 4 + i) * H_DIM + tx * 4) = v;
    }
}

// ---------------------------------------------------------------------------
extern "C" void kernel_launch(void* const* d_in, const int* in_sizes, int n_in,
                              void* d_out, int out_size)
{
    const float* x  = (const float*)d_in[0];
    const float* wq = (const float*)d_in[1];
    const float* wk = (const float*)d_in[2];
    const float* wv = (const float*)d_in[3];
    float* out = (float*)d_out;

    (void)in_sizes; (void)n_in; (void)out_size;

    static const size_t kAttnSmem = 4 * 64 * 64 * sizeof(float);  // 65536 B
    cudaFuncSetAttribute(attn_kernel,
                         cudaFuncAttributeMaxDynamicSharedMemorySize,
                         (int)kAttnSmem);

    // QKV projection: grid (M/64 = 512, 3 matrices)
    proj_kernel<<<dim3(M_ROWS / 64, 3), 256>>>(x, wq, wk, wv);

    // Attention: grid (32 q-tiles, 16 batches)
    attn_kernel<<<dim3(T_SEQ / 64, B_DIM), 256, kAttnSmem>>>(out);
}

// round 7
// speedup vs baseline: 2.2619x; 1.1927x over previous
#include <cuda_runtime.h>
#include <cuda_bf16.h>
#include <stdint.h>

// Problem constants
#define T_SEQ 2048
#define C_DIM 1024
#define H_DIM 64
#define B_DIM 16
#define M_ROWS (B_DIM * T_SEQ)   // 32768

// Scratch for Q/K/V projections (static device allocation — no cudaMalloc)
__device__ float g_q[M_ROWS * H_DIM];
__device__ float g_k[M_ROWS * H_DIM];
__device__ float g_v[M_ROWS * H_DIM];

// Pre-transposed (B[n=h][k]), hi/lo-split bf16 weights, padded stride 72.
// Tile per (matrix, k-chunk): 64 rows x 72 bf16 = 9216 bytes.
#define WT_STRIDE 72
__device__ __align__(16) unsigned short g_wt_hi[3][16][64 * WT_STRIDE];
__device__ __align__(16) unsigned short g_wt_lo[3][16][64 * WT_STRIDE];

// ---------------------------------------------------------------------------
// Warp-level bf16 MMA (standard PTX, compiles under compute_103 — no 'a'
// suffix features). D(f32) += A(bf16,row) * B(bf16,col).
// ---------------------------------------------------------------------------
__device__ __forceinline__ void mma_bf16(float* d, const uint32_t* a,
                                         uint32_t b0, uint32_t b1) {
    asm volatile(
        "mma.sync.aligned.m16n8k16.row.col.f32.bf16.bf16.f32 "
        "{%0,%1,%2,%3}, {%4,%5,%6,%7}, {%8,%9}, {%0,%1,%2,%3};"
        : "+f"(d[0]), "+f"(d[1]), "+f"(d[2]), "+f"(d[3])
        : "r"(a[0]), "r"(a[1]), "r"(a[2]), "r"(a[3]), "r"(b0), "r"(b1));
}

// ---------------------------------------------------------------------------
// Weight prep: w[k][h] -> B[n=h][k] (col-major for mma row.col), split into
// hi/lo bf16, padded stride 72 bf16. Grid: (16 k-chunks, 3 matrices).
// ---------------------------------------------------------------------------
__global__ __launch_bounds__(128) void wprep_kernel(
    const float* __restrict__ wq,
    const float* __restrict__ wk,
    const float* __restrict__ wv)
{
    const int chunk = blockIdx.x;
    const int m3    = blockIdx.y;
    const float* w = (m3 == 0) ? wq : (m3 == 1) ? wk : wv;
    unsigned short* dst_hi = g_wt_hi[m3][chunk];
    unsigned short* dst_lo = g_wt_lo[m3][chunk];
    const int tid = threadIdx.x;

    // 64 h-rows x 32 k-pairs = 2048 pairs
    for (int e = 0; e < 16; e++) {
        int p  = e * 128 + tid;
        int h  = p >> 5;          // 0..63
        int kk = (p & 31) * 2;    // even k within chunk
        float v0 = w[(size_t)(chunk * 64 + kk)     * H_DIM + h];
        float v1 = w[(size_t)(chunk * 64 + kk + 1) * H_DIM + h];
        __nv_bfloat16 h0 = __float2bfloat16(v0);
        __nv_bfloat16 h1 = __float2bfloat16(v1);
        __nv_bfloat16 l0 = __float2bfloat16(v0 - __bfloat162float(h0));
        __nv_bfloat16 l1 = __float2bfloat16(v1 - __bfloat162float(h1));
        uint32_t hp = ((uint32_t)__bfloat16_as_ushort(h1) << 16) | __bfloat16_as_ushort(h0);
        uint32_t lp = ((uint32_t)__bfloat16_as_ushort(l1) << 16) | __bfloat16_as_ushort(l0);
        *(uint32_t*)&dst_hi[h * WT_STRIDE + kk] = hp;
        *(uint32_t*)&dst_lo[h * WT_STRIDE + kk] = lp;
    }
}

// ---------------------------------------------------------------------------
// Projection via mma.sync: out[m][h] = sum_k x[m][k] * w[k][h], fp32 through
// a 3-term bf16 split (hi*hi + hi*lo + lo*hi), fp32 accumulators.
//
// Grid: 512 CTAs x 384 threads (12 warps). CTA owns 64 x-rows; warp w owns
// matrix w/4 (Q/K/V) and m-strip (w%4)*16. Per 64-k chunk: stage x hi/lo in
// smem (stride 72 bf16, conflict-free fragment LDS), copy prepped B tiles,
// then each warp does 4 k-steps x 8 n-tiles x 3 split-term MMAs.
// Fragment maps (PTX ISA, m16n8k16): g=lane>>2, t=lane&3.
//   A: a0=(g, 2t) a1=(g+8, 2t) a2=(g, 2t+8) a3=(g+8, 2t+8)   [pairs k,k+1]
//   B: b0=(k=2t, n=g) b1=(k=2t+8, n=g)                        [pairs k,k+1]
//   D: c0,c1=(g, 2t..2t+1) c2,c3=(g+8, 2t..2t+1)
// SMEM: A_hi@0, A_lo@9216, B tiles (m3: hi,lo)@18432+.. = 73728 B total.
// ---------------------------------------------------------------------------
#define SM_AHI 0
#define SM_ALO 9216
#define SM_BW  18432
#define PROJ_SMEM (18432 + 6 * 9216)   // 73728

__global__ __launch_bounds__(384, 2) void proj_mma_kernel(const float* __restrict__ x)
{
    extern __shared__ unsigned char smem[];
    unsigned short* Ah = (unsigned short*)(smem + SM_AHI);
    unsigned short* Al = (unsigned short*)(smem + SM_ALO);

    const int tid  = threadIdx.x;
    const int wid  = tid >> 5;
    const int lane = tid & 31;
    const int g    = lane >> 2;
    const int t    = lane & 3;
    const int m3   = wid >> 2;          // matrix 0..2
    const int mrow = (wid & 3) * 16;    // m-strip within CTA tile
    const int m0   = blockIdx.x * 64;

    const unsigned short* Bh = (unsigned short*)(smem + SM_BW + (m3 * 2 + 0) * 9216);
    const unsigned short* Bl = (unsigned short*)(smem + SM_BW + (m3 * 2 + 1) * 9216);

    float d[8][4] = {};   // 8 n-tiles x 4 f32

    for (int chunk = 0; chunk < 16; chunk++) {
        const int k0 = chunk * 64;

        // ---- Stage x chunk as hi/lo bf16 (64 rows x 64 k, stride 72) ----
        for (int p = tid; p < 2048; p += 384) {
            int r = p >> 5;               // row 0..63
            int c = (p & 31) * 2;         // even col
            float2 v = *(const float2*)&x[(size_t)(m0 + r) * C_DIM + k0 + c];
            __nv_bfloat16 h0 = __float2bfloat16(v.x);
            __nv_bfloat16 h1 = __float2bfloat16(v.y);
            __nv_bfloat16 l0 = __float2bfloat16(v.x - __bfloat162float(h0));
            __nv_bfloat16 l1 = __float2bfloat16(v.y - __bfloat162float(h1));
            uint32_t hp = ((uint32_t)__bfloat16_as_ushort(h1) << 16) | __bfloat16_as_ushort(h0);
            uint32_t lp = ((uint32_t)__bfloat16_as_ushort(l1) << 16) | __bfloat16_as_ushort(l0);
            *(uint32_t*)&Ah[r * WT_STRIDE + c] = hp;
            *(uint32_t*)&Al[r * WT_STRIDE + c] = lp;
        }

        // ---- Copy prepped B tiles: 6 x 9216B as uint2 (6912 total) ----
        for (int p = tid; p < 6912; p += 384) {
            int tile = p / 1152;          // 0..5  (m3*2 + hi/lo)
            int i    = p - tile * 1152;
            int tm   = tile >> 1;
            const unsigned short* src = (tile & 1) ? g_wt_lo[tm][chunk]
                                                   : g_wt_hi[tm][chunk];
            *(uint2*)(smem + SM_BW + tile * 9216 + i * 8) =
                *(const uint2*)(src + i * 4);
        }
        __syncthreads();

        // ---- MMAs: 4 k-steps x 8 n-tiles x 3 split terms ----
        #pragma unroll
        for (int ks = 0; ks < 4; ks++) {
            const int kb = ks * 16;
            uint32_t ah[4], al4[4];
            const int r0 = mrow + g, r1 = mrow + g + 8;
            const int ca = kb + t * 2, cb = kb + t * 2 + 8;
            ah[0] = *(const uint32_t*)&Ah[r0 * WT_STRIDE + ca];
            ah[1] = *(const uint32_t*)&Ah[r1 * WT_STRIDE + ca];
            ah[2] = *(const uint32_t*)&Ah[r0 * WT_STRIDE + cb];
            ah[3] = *(const uint32_t*)&Ah[r1 * WT_STRIDE + cb];
            al4[0] = *(const uint32_t*)&Al[r0 * WT_STRIDE + ca];
            al4[1] = *(const uint32_t*)&Al[r1 * WT_STRIDE + ca];
            al4[2] = *(const uint32_t*)&Al[r0 * WT_STRIDE + cb];
            al4[3] = *(const uint32_t*)&Al[r1 * WT_STRIDE + cb];
            #pragma unroll
            for (int nt = 0; nt < 8; nt++) {
                const int n = nt * 8 + g;
                uint32_t bh0 = *(const uint32_t*)&Bh[n * WT_STRIDE + ca];
                uint32_t bh1 = *(const uint32_t*)&Bh[n * WT_STRIDE + cb];
                uint32_t bl0 = *(const uint32_t*)&Bl[n * WT_STRIDE + ca];
                uint32_t bl1 = *(const uint32_t*)&Bl[n * WT_STRIDE + cb];
                mma_bf16(d[nt], ah, bh0, bh1);   // hi*hi
                mma_bf16(d[nt], ah, bl0, bl1);   // hi*lo
                mma_bf16(d[nt], al4, bh0, bh1);  // lo*hi
            }
        }
        __syncthreads();  // protect smem before next chunk's restage
    }

    // ---- Epilogue: write D fragments to g_q/g_k/g_v ----
    float* outp = (m3 == 0) ? g_q : (m3 == 1) ? g_k : g_v;
    const int grow0 = m0 + mrow + g;
    #pragma unroll
    for (int nt = 0; nt < 8; nt++) {
        const int col = nt * 8 + t * 2;
        *(float2*)&outp[(size_t)grow0 * H_DIM + col] =
            make_float2(d[nt][0], d[nt][1]);
        *(float2*)&outp[(size_t)(grow0 + 8) * H_DIM + col] =
            make_float2(d[nt][2], d[nt][3]);
    }
}

// ---------------------------------------------------------------------------
// Flash attention (causal), fp32, online softmax — unchanged from Round 3
// (measured 322 us, ~near its SIMT issue ceiling).
// ---------------------------------------------------------------------------
__global__ __launch_bounds__(256, 2) void attn_kernel(float* __restrict__ out)
{
    extern __shared__ float sm[];
    float* Qs = sm;           // [64][64] pre-scaled by 0.125
    float* Ks = sm + 4096;    // [64][64] XOR-swizzled chunks
    float* Vs = sm + 8192;    // [64][64] plain
    float* Ps = sm + 12288;   // [64][64]

    const int b    = blockIdx.y;
    const int qt   = gridDim.x - 1 - blockIdx.x;   // heavy tiles first
    const int q0   = qt * 64;
    const int tid  = threadIdx.x;
    const int tx   = tid & 15;   // col group
    const int ty   = tid >> 4;   // row group

    const float* qb = g_q + (size_t)b * T_SEQ * H_DIM;
    const float* kb = g_k + (size_t)b * T_SEQ * H_DIM;
    const float* vb = g_v + (size_t)b * T_SEQ * H_DIM;

    #pragma unroll
    for (int rep = 0; rep < 4; rep++) {
        int f  = tid + rep * 256;
        int r  = f >> 4;
        int kk = f & 15;
        float4 q = *(const float4*)&qb[(size_t)(q0 + r) * H_DIM + kk * 4];
        q.x *= 0.125f; q.y *= 0.125f; q.z *= 0.125f; q.w *= 0.125f;
        *(float4*)&Qs[r * 64 + kk * 4] = q;
    }

    float o[4][4] = {};
    float m_r[4], l_r[4];
    #pragma unroll
    for (int i = 0; i < 4; i++) { m_r[i] = -1e30f; l_r[i] = 0.0f; }

    __syncthreads();

    for (int j0 = 0; j0 <= q0; j0 += 64) {
        #pragma unroll
        for (int rep = 0; rep < 4; rep++) {
            int f  = tid + rep * 256;
            int c  = f >> 4;
            int kk = f & 15;
            float4 kv = *(const float4*)&kb[(size_t)(j0 + c) * H_DIM + kk * 4];
            float4 vv = *(const float4*)&vb[(size_t)(j0 + c) * H_DIM + kk * 4];
            *(float4*)&Ks[c * 64 + (((kk ^ (c >> 2)) & 15) << 2)] = kv;
            *(float4*)&Vs[c * 64 + kk * 4]                        = vv;
        }
        __syncthreads();

        float s[4][4] = {};
        #pragma unroll
        for (int h4 = 0; h4 < 16; h4++) {
            float4 q4[4], k4[4];
            #pragma unroll
            for (int i = 0; i < 4; i++)
                q4[i] = *(float4*)&Qs[(ty * 4 + i) * 64 + h4 * 4];
            #pragma unroll
            for (int j = 0; j < 4; j++) {
                int r = tx * 4 + j;
                k4[j] = *(float4*)&Ks[r * 64 + (((h4 ^ (r >> 2)) & 15) << 2)];
            }
            #pragma unroll
            for (int i = 0; i < 4; i++) {
                #pragma unroll
                for (int j = 0; j < 4; j++) {
                    s[i][j] += q4[i].x * k4[j].x;
                    s[i][j] += q4[i].y * k4[j].y;
                    s[i][j] += q4[i].z * k4[j].z;
                    s[i][j] += q4[i].w * k4[j].w;
                }
            }
        }

        if (j0 == q0) {
            #pragma unroll
            for (int i = 0; i < 4; i++)
                #pragma unroll
                for (int j = 0; j < 4; j++)
                    if (tx * 4 + j > ty * 4 + i) s[i][j] = -1e30f;
        }

        float mt[4], rs[4], alpha[4];
        #pragma unroll
        for (int i = 0; i < 4; i++)
            mt[i] = fmaxf(fmaxf(s[i][0], s[i][1]), fmaxf(s[i][2], s[i][3]));
        #pragma unroll
        for (int off = 8; off > 0; off >>= 1) {
            #pragma unroll
            for (int i = 0; i < 4; i++)
                mt[i] = fmaxf(mt[i], __shfl_xor_sync(0xffffffffu, mt[i], off));
        }
        #pragma unroll
        for (int i = 0; i < 4; i++) {
            float m_new = fmaxf(m_r[i], mt[i]);
            alpha[i] = __expf(m_r[i] - m_new);
            m_r[i]   = m_new;
            s[i][0] = __expf(s[i][0] - m_new);
            s[i][1] = __expf(s[i][1] - m_new);
            s[i][2] = __expf(s[i][2] - m_new);
            s[i][3] = __expf(s[i][3] - m_new);
            rs[i] = (s[i][0] + s[i][1]) + (s[i][2] + s[i][3]);
        }
        #pragma unroll
        for (int off = 8; off > 0; off >>= 1) {
            #pragma unroll
            for (int i = 0; i < 4; i++)
                rs[i] += __shfl_xor_sync(0xffffffffu, rs[i], off);
        }
        #pragma unroll
        for (int i = 0; i < 4; i++) {
            l_r[i] = l_r[i] * alpha[i] + rs[i];
            o[i][0] *= alpha[i]; o[i][1] *= alpha[i];
            o[i][2] *= alpha[i]; o[i][3] *= alpha[i];
            *(float4*)&Ps[(ty * 4 + i) * 64 + tx * 4] =
                make_float4(s[i][0], s[i][1], s[i][2], s[i][3]);
        }
        __syncthreads();

        #pragma unroll
        for (int j4 = 0; j4 < 16; j4++) {
            float4 p4[4];
            #pragma unroll
            for (int i = 0; i < 4; i++)
                p4[i] = *(float4*)&Ps[(ty * 4 + i) * 64 + j4 * 4];
            #pragma unroll
            for (int jj = 0; jj < 4; jj++) {
                float4 v4 = *(float4*)&Vs[(j4 * 4 + jj) * 64 + tx * 4];
                #pragma unroll
                for (int i = 0; i < 4; i++) {
                    float p = (&p4[i].x)[jj];
                    o[i][0] += p * v4.x;
                    o[i][1] += p * v4.y;
                    o[i][2] += p * v4.z;
                    o[i][3] += p * v4.w;
                }
            }
        }
        __syncthreads();
    }

    #pragma unroll
    for (int i = 0; i < 4; i++) {
        float inv = 1.0f / l_r[i];
        float4 v = make_float4(o[i][0] * inv, o[i][1] * inv,
                               o[i][2] * inv, o[i][3] * inv);
        *(float4*)(out + ((size_t)b * T_SEQ + q0 + ty * 4 + i) * H_DIM + tx * 4) = v;
    }
}

// ---------------------------------------------------------------------------
extern "C" void kernel_launch(void* const* d_in, const int* in_sizes, int n_in,
                              void* d_out, int out_size)
{
    const float* x  = (const float*)d_in[0];
    const float* wq = (const float*)d_in[1];
    const float* wk = (const float*)d_in[2];
    const float* wv = (const float*)d_in[3];
    float* out = (float*)d_out;

    (void)in_sizes; (void)n_in; (void)out_size;

    static const size_t kAttnSmem = 4 * 64 * 64 * sizeof(float);  // 65536 B
    cudaFuncSetAttribute(attn_kernel,
                         cudaFuncAttributeMaxDynamicSharedMemorySize,
                         (int)kAttnSmem);
    cudaFuncSetAttribute(proj_mma_kernel,
                         cudaFuncAttributeMaxDynamicSharedMemorySize,
                         PROJ_SMEM);

    // 1) Prep transposed/split/padded weights (tiny)
    wprep_kernel<<<dim3(16, 3), 128>>>(wq, wk, wv);

    // 2) QKV projection via warp-level bf16 MMA
    proj_mma_kernel<<<M_ROWS / 64, 384, PROJ_SMEM>>>(x);

    // 3) Attention: grid (32 q-tiles, 16 batches)
    attn_kernel<<<dim3(T_SEQ / 64, B_DIM), 256, kAttnSmem>>>(out);
}

// round 8
// speedup vs baseline: 3.6116x; 1.5968x over previous
#include <cuda_runtime.h>
#include <cuda_bf16.h>
#include <stdint.h>

// Problem constants
#define T_SEQ 2048
#define C_DIM 1024
#define H_DIM 64
#define B_DIM 16
#define M_ROWS (B_DIM * T_SEQ)   // 32768

// Q/K stored as split bf16 (value = hi + lo), row-major [m][h].
// Q is pre-scaled by 1/sqrt(H) = 0.125. V stored TRANSPOSED: [h][m].
__device__ unsigned short g_qh[M_ROWS * H_DIM];
__device__ unsigned short g_ql[M_ROWS * H_DIM];
__device__ unsigned short g_kh[M_ROWS * H_DIM];
__device__ unsigned short g_kl[M_ROWS * H_DIM];
__device__ unsigned short g_vth[H_DIM * M_ROWS];
__device__ unsigned short g_vtl[H_DIM * M_ROWS];

// Pre-transposed (B[n=h][k]), hi/lo-split bf16 weights, padded stride 72.
#define WT_STRIDE 72
__device__ __align__(16) unsigned short g_wt_hi[3][16][64 * WT_STRIDE];
__device__ __align__(16) unsigned short g_wt_lo[3][16][64 * WT_STRIDE];

// ---------------------------------------------------------------------------
// Warp-level bf16 MMA (standard PTX; validated on this toolchain in R7).
// D(f32) += A(bf16,row) * B(bf16,col).
// Fragment maps (g=lane>>2, t=lane&3):
//   A: a0=(g,2t) a1=(g+8,2t) a2=(g,2t+8) a3=(g+8,2t+8)   [bf16 pairs k,k+1]
//   B: b0=(k=2t,n=g) b1=(k=2t+8,n=g)                     [pairs k,k+1]
//   D: c0,c1=(g,2t..2t+1) c2,c3=(g+8,2t..2t+1)
// ---------------------------------------------------------------------------
__device__ __forceinline__ void mma_bf16(float* d, const uint32_t* a,
                                         uint32_t b0, uint32_t b1) {
    asm volatile(
        "mma.sync.aligned.m16n8k16.row.col.f32.bf16.bf16.f32 "
        "{%0,%1,%2,%3}, {%4,%5,%6,%7}, {%8,%9}, {%0,%1,%2,%3};"
        : "+f"(d[0]), "+f"(d[1]), "+f"(d[2]), "+f"(d[3])
        : "r"(a[0]), "r"(a[1]), "r"(a[2]), "r"(a[3]), "r"(b0), "r"(b1));
}

__device__ __forceinline__ void split2(float a, float b, uint32_t& hi, uint32_t& lo) {
    __nv_bfloat16 ah = __float2bfloat16(a), bh = __float2bfloat16(b);
    __nv_bfloat16 al = __float2bfloat16(a - __bfloat162float(ah));
    __nv_bfloat16 bl = __float2bfloat16(b - __bfloat162float(bh));
    hi = ((uint32_t)__bfloat16_as_ushort(bh) << 16) | __bfloat16_as_ushort(ah);
    lo = ((uint32_t)__bfloat16_as_ushort(bl) << 16) | __bfloat16_as_ushort(al);
}

__device__ __forceinline__ uint32_t bpack(float a, float b) {
    return ((uint32_t)__bfloat16_as_ushort(__float2bfloat16(b)) << 16)
         | __bfloat16_as_ushort(__float2bfloat16(a));
}
__device__ __forceinline__ float bf_lo(float a) {
    return a - __bfloat162float(__float2bfloat16(a));
}

// ---------------------------------------------------------------------------
// Weight prep: w[k][h] -> B[n=h][k] col-major, hi/lo split, stride 72.
// ---------------------------------------------------------------------------
__global__ __launch_bounds__(128) void wprep_kernel(
    const float* __restrict__ wq,
    const float* __restrict__ wk,
    const float* __restrict__ wv)
{
    const int chunk = blockIdx.x;
    const int m3    = blockIdx.y;
    const float* w = (m3 == 0) ? wq : (m3 == 1) ? wk : wv;
    unsigned short* dst_hi = g_wt_hi[m3][chunk];
    unsigned short* dst_lo = g_wt_lo[m3][chunk];
    const int tid = threadIdx.x;

    for (int e = 0; e < 16; e++) {
        int p  = e * 128 + tid;
        int h  = p >> 5;
        int kk = (p & 31) * 2;
        float v0 = w[(size_t)(chunk * 64 + kk)     * H_DIM + h];
        float v1 = w[(size_t)(chunk * 64 + kk + 1) * H_DIM + h];
        uint32_t hp, lp;
        split2(v0, v1, hp, lp);
        *(uint32_t*)&dst_hi[h * WT_STRIDE + kk] = hp;
        *(uint32_t*)&dst_lo[h * WT_STRIDE + kk] = lp;
    }
}

// ---------------------------------------------------------------------------
// Projection via mma.sync (3-term bf16 split). Epilogue now stores Q (scaled
// by 0.125), K as split bf16 row-major, and V as split bf16 TRANSPOSED so the
// attention kernel's staging is raw copies.
// ---------------------------------------------------------------------------
#define SM_AHI 0
#define SM_ALO 9216
#define SM_BW  18432
#define PROJ_SMEM (18432 + 6 * 9216)   // 73728

__global__ __launch_bounds__(384, 2) void proj_mma_kernel(const float* __restrict__ x)
{
    extern __shared__ unsigned char smem[];
    unsigned short* Ah = (unsigned short*)(smem + SM_AHI);
    unsigned short* Al = (unsigned short*)(smem + SM_ALO);

    const int tid  = threadIdx.x;
    const int wid  = tid >> 5;
    const int lane = tid & 31;
    const int g    = lane >> 2;
    const int t    = lane & 3;
    const int m3   = wid >> 2;          // matrix 0..2
    const int mrow = (wid & 3) * 16;    // m-strip within CTA tile
    const int m0   = blockIdx.x * 64;

    const unsigned short* Bh = (unsigned short*)(smem + SM_BW + (m3 * 2 + 0) * 9216);
    const unsigned short* Bl = (unsigned short*)(smem + SM_BW + (m3 * 2 + 1) * 9216);

    float d[8][4] = {};

    for (int chunk = 0; chunk < 16; chunk++) {
        const int k0 = chunk * 64;

        // Stage x chunk as hi/lo bf16 (64 rows x 64 k, stride 72)
        for (int p = tid; p < 2048; p += 384) {
            int r = p >> 5;
            int c = (p & 31) * 2;
            float2 v = *(const float2*)&x[(size_t)(m0 + r) * C_DIM + k0 + c];
            uint32_t hp, lp;
            split2(v.x, v.y, hp, lp);
            *(uint32_t*)&Ah[r * WT_STRIDE + c] = hp;
            *(uint32_t*)&Al[r * WT_STRIDE + c] = lp;
        }

        // Copy prepped B tiles: 6 x 9216B as uint2
        for (int p = tid; p < 6912; p += 384) {
            int tile = p / 1152;
            int i    = p - tile * 1152;
            int tm   = tile >> 1;
            const unsigned short* src = (tile & 1) ? g_wt_lo[tm][chunk]
                                                   : g_wt_hi[tm][chunk];
            *(uint2*)(smem + SM_BW + tile * 9216 + i * 8) =
                *(const uint2*)(src + i * 4);
        }
        __syncthreads();

        #pragma unroll
        for (int ks = 0; ks < 4; ks++) {
            const int kb = ks * 16;
            uint32_t ah[4], al4[4];
            const int r0 = mrow + g, r1 = mrow + g + 8;
            const int ca = kb + t * 2, cb = kb + t * 2 + 8;
            ah[0] = *(const uint32_t*)&Ah[r0 * WT_STRIDE + ca];
            ah[1] = *(const uint32_t*)&Ah[r1 * WT_STRIDE + ca];
            ah[2] = *(const uint32_t*)&Ah[r0 * WT_STRIDE + cb];
            ah[3] = *(const uint32_t*)&Ah[r1 * WT_STRIDE + cb];
            al4[0] = *(const uint32_t*)&Al[r0 * WT_STRIDE + ca];
            al4[1] = *(const uint32_t*)&Al[r1 * WT_STRIDE + ca];
            al4[2] = *(const uint32_t*)&Al[r0 * WT_STRIDE + cb];
            al4[3] = *(const uint32_t*)&Al[r1 * WT_STRIDE + cb];
            #pragma unroll
            for (int nt = 0; nt < 8; nt++) {
                const int n = nt * 8 + g;
                uint32_t bh0 = *(const uint32_t*)&Bh[n * WT_STRIDE + ca];
                uint32_t bh1 = *(const uint32_t*)&Bh[n * WT_STRIDE + cb];
                uint32_t bl0 = *(const uint32_t*)&Bl[n * WT_STRIDE + ca];
                uint32_t bl1 = *(const uint32_t*)&Bl[n * WT_STRIDE + cb];
                mma_bf16(d[nt], ah, bh0, bh1);
                mma_bf16(d[nt], ah, bl0, bl1);
                mma_bf16(d[nt], al4, bh0, bh1);
            }
        }
        __syncthreads();
    }

    // ---- Epilogue: split to bf16 and store ----
    const int grow0 = m0 + mrow + g;
    if (m3 == 0) {
        #pragma unroll
        for (int nt = 0; nt < 8; nt++) {
            int col = nt * 8 + t * 2;
            uint32_t h0, l0, h1, l1;
            split2(d[nt][0] * 0.125f, d[nt][1] * 0.125f, h0, l0);
            split2(d[nt][2] * 0.125f, d[nt][3] * 0.125f, h1, l1);
            *(uint32_t*)&g_qh[(size_t)grow0 * 64 + col] = h0;
            *(uint32_t*)&g_ql[(size_t)grow0 * 64 + col] = l0;
            *(uint32_t*)&g_qh[(size_t)(grow0 + 8) * 64 + col] = h1;
            *(uint32_t*)&g_ql[(size_t)(grow0 + 8) * 64 + col] = l1;
        }
    } else if (m3 == 1) {
        #pragma unroll
        for (int nt = 0; nt < 8; nt++) {
            int col = nt * 8 + t * 2;
            uint32_t h0, l0, h1, l1;
            split2(d[nt][0], d[nt][1], h0, l0);
            split2(d[nt][2], d[nt][3], h1, l1);
            *(uint32_t*)&g_kh[(size_t)grow0 * 64 + col] = h0;
            *(uint32_t*)&g_kl[(size_t)grow0 * 64 + col] = l0;
            *(uint32_t*)&g_kh[(size_t)(grow0 + 8) * 64 + col] = h1;
            *(uint32_t*)&g_kl[(size_t)(grow0 + 8) * 64 + col] = l1;
        }
    } else {
        // V: store transposed [h][m]
        #pragma unroll
        for (int nt = 0; nt < 8; nt++) {
            int col = nt * 8 + t * 2;
            #pragma unroll
            for (int c = 0; c < 4; c++) {
                int cc = col + (c & 1);
                int rr = grow0 + (c >> 1) * 8;
                float v = d[nt][c];
                __nv_bfloat16 vh = __float2bfloat16(v);
                float vl = v - __bfloat162float(vh);
                g_vth[(size_t)cc * M_ROWS + rr] = __bfloat16_as_ushort(vh);
                g_vtl[(size_t)cc * M_ROWS + rr] =
                    __bfloat16_as_ushort(__float2bfloat16(vl));
            }
        }
    }
}

// ---------------------------------------------------------------------------
// Flash attention on mma.sync. CTA: 128 threads (4 warps), BQ=64, BK=64.
// Warp w owns q-rows [w*16, w*16+16). Q fragments loaded once from global
// into registers. Per k-tile: stage K hi/lo [key][h] and V^T hi/lo [h][s]
// (raw uint4 copies, stride 72 shorts -> conflict-free fragment LDS,
// bank = 4g + t), QK^T via 3-term split MMA, softmax on D fragments
// (stats reduced over the 4-lane t-group), P re-split hi/lo in registers
// (S D-fragment layout == PV A-fragment layout, no smem round trip),
// PV via 3-term split MMA into O fragments.
// Smem 36864 B, occupancy 3. Grid (32 reversed q-tiles, 16 batches).
// ---------------------------------------------------------------------------
#define ATT_SMEM (4 * 64 * 72 * 2)   // 36864

__global__ __launch_bounds__(128, 3) void attn_mma_kernel(float* __restrict__ out)
{
    extern __shared__ unsigned short smA[];
    unsigned short* Kh = smA;             // [key][h] stride 72
    unsigned short* Kl = smA + 4608;
    unsigned short* Vh = smA + 9216;      // [h][s] stride 72
    unsigned short* Vl = smA + 13824;

    const int tid  = threadIdx.x;
    const int warp = tid >> 5;
    const int lane = tid & 31;
    const int g    = lane >> 2;
    const int t    = lane & 3;
    const int b    = blockIdx.y;
    const int qt   = gridDim.x - 1 - blockIdx.x;   // heavy tiles first
    const int q0   = qt * 64;
    const int mrow = warp * 16;
    const size_t mb = (size_t)b * T_SEQ;

    // ---- Q fragments (loop-invariant): [ks][4], hi and lo ----
    uint32_t qh[4][4], ql[4][4];
    {
        const int r0 = q0 + mrow + g;
        #pragma unroll
        for (int ks = 0; ks < 4; ks++) {
            const size_t o0 = (mb + r0) * 64 + ks * 16 + 2 * t;
            const size_t o1 = o0 + 8 * 64;
            qh[ks][0] = *(const uint32_t*)&g_qh[o0];
            qh[ks][1] = *(const uint32_t*)&g_qh[o1];
            qh[ks][2] = *(const uint32_t*)&g_qh[o0 + 8];
            qh[ks][3] = *(const uint32_t*)&g_qh[o1 + 8];
            ql[ks][0] = *(const uint32_t*)&g_ql[o0];
            ql[ks][1] = *(const uint32_t*)&g_ql[o1];
            ql[ks][2] = *(const uint32_t*)&g_ql[o0 + 8];
            ql[ks][3] = *(const uint32_t*)&g_ql[o1 + 8];
        }
    }

    float o[8][4] = {};
    float m_r[2] = {-1e30f, -1e30f};
    float l_r[2] = {0.0f, 0.0f};

    for (int j0 = 0; j0 <= q0; j0 += 64) {
        // ---- Stage K hi/lo and V^T hi/lo (2048 uint4 over 128 threads) ----
        #pragma unroll
        for (int e = 0; e < 16; e++) {
            int p    = e * 128 + tid;
            int tile = p >> 9;
            int i    = p & 511;
            int row  = i >> 3;
            int c8   = i & 7;
            const unsigned short* src;
            if (tile == 0)      src = &g_kh[(mb + j0 + row) * 64 + c8 * 8];
            else if (tile == 1) src = &g_kl[(mb + j0 + row) * 64 + c8 * 8];
            else if (tile == 2) src = &g_vth[(size_t)row * M_ROWS + mb + j0 + c8 * 8];
            else                src = &g_vtl[(size_t)row * M_ROWS + mb + j0 + c8 * 8];
            *(uint4*)&smA[tile * 4608 + row * 72 + c8 * 8] = *(const uint4*)src;
        }
        __syncthreads();

        // ---- S = Q K^T (3-term split) ----
        float s[8][4] = {};
        #pragma unroll
        for (int ks = 0; ks < 4; ks++) {
            const int ca = ks * 16 + 2 * t, cb = ca + 8;
            #pragma unroll
            for (int nt = 0; nt < 8; nt++) {
                const int n = nt * 8 + g;
                uint32_t bh0 = *(const uint32_t*)&Kh[n * 72 + ca];
                uint32_t bh1 = *(const uint32_t*)&Kh[n * 72 + cb];
                uint32_t bl0 = *(const uint32_t*)&Kl[n * 72 + ca];
                uint32_t bl1 = *(const uint32_t*)&Kl[n * 72 + cb];
                mma_bf16(s[nt], qh[ks], bh0, bh1);
                mma_bf16(s[nt], qh[ks], bl0, bl1);
                mma_bf16(s[nt], ql[ks], bh0, bh1);
            }
        }

        // ---- Causal mask (diagonal tile only) ----
        if (j0 == q0) {
            #pragma unroll
            for (int nt = 0; nt < 8; nt++) {
                #pragma unroll
                for (int c = 0; c < 4; c++) {
                    int col = nt * 8 + 2 * t + (c & 1);
                    int row = mrow + g + (c >> 1) * 8;
                    if (col > row) s[nt][c] = -1e30f;
                }
            }
        }

        // ---- Online softmax on fragments ----
        float mt0 = -1e30f, mt1 = -1e30f;
        #pragma unroll
        for (int nt = 0; nt < 8; nt++) {
            mt0 = fmaxf(mt0, fmaxf(s[nt][0], s[nt][1]));
            mt1 = fmaxf(mt1, fmaxf(s[nt][2], s[nt][3]));
        }
        mt0 = fmaxf(mt0, __shfl_xor_sync(0xffffffffu, mt0, 1));
        mt0 = fmaxf(mt0, __shfl_xor_sync(0xffffffffu, mt0, 2));
        mt1 = fmaxf(mt1, __shfl_xor_sync(0xffffffffu, mt1, 1));
        mt1 = fmaxf(mt1, __shfl_xor_sync(0xffffffffu, mt1, 2));

        float mn0 = fmaxf(m_r[0], mt0);
        float mn1 = fmaxf(m_r[1], mt1);
        float a0 = __expf(m_r[0] - mn0);
        float a1 = __expf(m_r[1] - mn1);
        m_r[0] = mn0; m_r[1] = mn1;

        float rs0 = 0.0f, rs1 = 0.0f;
        #pragma unroll
        for (int nt = 0; nt < 8; nt++) {
            s[nt][0] = __expf(s[nt][0] - mn0);
            s[nt][1] = __expf(s[nt][1] - mn0);
            s[nt][2] = __expf(s[nt][2] - mn1);
            s[nt][3] = __expf(s[nt][3] - mn1);
            rs0 += s[nt][0] + s[nt][1];
            rs1 += s[nt][2] + s[nt][3];
        }
        rs0 += __shfl_xor_sync(0xffffffffu, rs0, 1);
        rs0 += __shfl_xor_sync(0xffffffffu, rs0, 2);
        rs1 += __shfl_xor_sync(0xffffffffu, rs1, 1);
        rs1 += __shfl_xor_sync(0xffffffffu, rs1, 2);
        l_r[0] = l_r[0] * a0 + rs0;
        l_r[1] = l_r[1] * a1 + rs1;

        #pragma unroll
        for (int nt = 0; nt < 8; nt++) {
            o[nt][0] *= a0; o[nt][1] *= a0;
            o[nt][2] *= a1; o[nt][3] *= a1;
        }

        // ---- O += P V (3-term split, P from registers) ----
        #pragma unroll
        for (int ks = 0; ks < 4; ks++) {
            uint32_t ph[4], pl[4];
            const int n0 = 2 * ks, n1 = 2 * ks + 1;
            ph[0] = bpack(s[n0][0], s[n0][1]);
            ph[1] = bpack(s[n0][2], s[n0][3]);
            ph[2] = bpack(s[n1][0], s[n1][1]);
            ph[3] = bpack(s[n1][2], s[n1][3]);
            pl[0] = bpack(bf_lo(s[n0][0]), bf_lo(s[n0][1]));
            pl[1] = bpack(bf_lo(s[n0][2]), bf_lo(s[n0][3]));
            pl[2] = bpack(bf_lo(s[n1][0]), bf_lo(s[n1][1]));
            pl[3] = bpack(bf_lo(s[n1][2]), bf_lo(s[n1][3]));
            const int ca = ks * 16 + 2 * t, cb = ca + 8;
            #pragma unroll
            for (int nt = 0; nt < 8; nt++) {
                const int n = nt * 8 + g;
                uint32_t bh0 = *(const uint32_t*)&Vh[n * 72 + ca];
                uint32_t bh1 = *(const uint32_t*)&Vh[n * 72 + cb];
                uint32_t bl0 = *(const uint32_t*)&Vl[n * 72 + ca];
                uint32_t bl1 = *(const uint32_t*)&Vl[n * 72 + cb];
                mma_bf16(o[nt], ph, bh0, bh1);
                mma_bf16(o[nt], ph, bl0, bl1);
                mma_bf16(o[nt], pl, bh0, bh1);
            }
        }
        __syncthreads();   // protect smem before next tile's staging
    }

    // ---- Finalize: divide by l, write out ----
    const float inv0 = 1.0f / l_r[0];
    const float inv1 = 1.0f / l_r[1];
    const size_t r0 = mb + q0 + mrow + g;
    #pragma unroll
    for (int nt = 0; nt < 8; nt++) {
        const int col = nt * 8 + 2 * t;
        *(float2*)&out[r0 * 64 + col] =
            make_float2(o[nt][0] * inv0, o[nt][1] * inv0);
        *(float2*)&out[(r0 + 8) * 64 + col] =
            make_float2(o[nt][2] * inv1, o[nt][3] * inv1);
    }
}

// ---------------------------------------------------------------------------
extern "C" void kernel_launch(void* const* d_in, const int* in_sizes, int n_in,
                              void* d_out, int out_size)
{
    const float* x  = (const float*)d_in[0];
    const float* wq = (const float*)d_in[1];
    const float* wk = (const float*)d_in[2];
    const float* wv = (const float*)d_in[3];
    float* out = (float*)d_out;

    (void)in_sizes; (void)n_in; (void)out_size;

    cudaFuncSetAttribute(proj_mma_kernel,
                         cudaFuncAttributeMaxDynamicSharedMemorySize, PROJ_SMEM);
    cudaFuncSetAttribute(attn_mma_kernel,
                         cudaFuncAttributeMaxDynamicSharedMemorySize, ATT_SMEM);

    // 1) Prep transposed/split/padded weights (tiny)
    wprep_kernel<<<dim3(16, 3), 128>>>(wq, wk, wv);

    // 2) QKV projection via warp-level bf16 MMA (writes split-bf16 Q/K/V^T)
    proj_mma_kernel<<<M_ROWS / 64, 384, PROJ_SMEM>>>(x);

    // 3) Attention on mma.sync: grid (32 q-tiles reversed, 16 batches)
    attn_mma_kernel<<<dim3(T_SEQ / 64, B_DIM), 128, ATT_SMEM>>>(out);
}

// round 9
// speedup vs baseline: 4.9885x; 1.3812x over previous
#include <cuda_runtime.h>
#include <cuda_bf16.h>
#include <stdint.h>

// Problem constants
#define T_SEQ 2048
#define C_DIM 1024
#define H_DIM 64
#define B_DIM 16
#define M_ROWS (B_DIM * T_SEQ)   // 32768

// Q/K stored as split bf16 (value = hi + lo), row-major [m][h].
// Q is pre-scaled by 1/sqrt(H) = 0.125. V stored TRANSPOSED: [h][m].
__device__ unsigned short g_qh[M_ROWS * H_DIM];
__device__ unsigned short g_ql[M_ROWS * H_DIM];
__device__ unsigned short g_kh[M_ROWS * H_DIM];
__device__ unsigned short g_kl[M_ROWS * H_DIM];
__device__ unsigned short g_vth[H_DIM * M_ROWS];
__device__ unsigned short g_vtl[H_DIM * M_ROWS];

// Pre-transposed (B[n=h][k]), hi/lo-split bf16 weights, padded stride 72.
#define WT_STRIDE 72
__device__ __align__(16) unsigned short g_wt_hi[3][16][64 * WT_STRIDE];
__device__ __align__(16) unsigned short g_wt_lo[3][16][64 * WT_STRIDE];

// ---------------------------------------------------------------------------
// Warp-level bf16 MMA (standard PTX; validated R7/R8).
// Fragment maps (g=lane>>2, t=lane&3):
//   A: a0=(g,2t) a1=(g+8,2t) a2=(g,2t+8) a3=(g+8,2t+8)   [bf16 pairs k,k+1]
//   B: b0=(k=2t,n=g) b1=(k=2t+8,n=g)
//   D: c0,c1=(g,2t..2t+1) c2,c3=(g+8,2t..2t+1)
// ---------------------------------------------------------------------------
__device__ __forceinline__ void mma_bf16(float* d, const uint32_t* a,
                                         uint32_t b0, uint32_t b1) {
    asm volatile(
        "mma.sync.aligned.m16n8k16.row.col.f32.bf16.bf16.f32 "
        "{%0,%1,%2,%3}, {%4,%5,%6,%7}, {%8,%9}, {%0,%1,%2,%3};"
        : "+f"(d[0]), "+f"(d[1]), "+f"(d[2]), "+f"(d[3])
        : "r"(a[0]), "r"(a[1]), "r"(a[2]), "r"(a[3]), "r"(b0), "r"(b1));
}

__device__ __forceinline__ void split2(float a, float b, uint32_t& hi, uint32_t& lo) {
    __nv_bfloat16 ah = __float2bfloat16(a), bh = __float2bfloat16(b);
    __nv_bfloat16 al = __float2bfloat16(a - __bfloat162float(ah));
    __nv_bfloat16 bl = __float2bfloat16(b - __bfloat162float(bh));
    hi = ((uint32_t)__bfloat16_as_ushort(bh) << 16) | __bfloat16_as_ushort(ah);
    lo = ((uint32_t)__bfloat16_as_ushort(bl) << 16) | __bfloat16_as_ushort(al);
}

__device__ __forceinline__ uint32_t bpack(float a, float b) {
    return ((uint32_t)__bfloat16_as_ushort(__float2bfloat16(b)) << 16)
         | __bfloat16_as_ushort(__float2bfloat16(a));
}
__device__ __forceinline__ float bf_lo(float a) {
    return a - __bfloat162float(__float2bfloat16(a));
}

__device__ __forceinline__ uint32_t smem_u32(const void* p) {
    uint32_t a;
    asm("{ .reg .u64 t; cvta.to.shared.u64 t, %1; cvt.u32.u64 %0, t; }"
        : "=r"(a) : "l"(p));
    return a;
}

__device__ __forceinline__ void cp_async16(uint32_t smem_dst, const void* gmem_src) {
    asm volatile("cp.async.cg.shared.global [%0], [%1], 16;"
                 :: "r"(smem_dst), "l"(gmem_src));
}
#define CP_COMMIT()  asm volatile("cp.async.commit_group;")
#define CP_WAIT1()   asm volatile("cp.async.wait_group 1;")
#define CP_WAIT0()   asm volatile("cp.async.wait_group 0;")

// ---------------------------------------------------------------------------
// Weight prep: w[k][h] -> B[n=h][k] col-major, hi/lo split, stride 72.
// ---------------------------------------------------------------------------
__global__ __launch_bounds__(128) void wprep_kernel(
    const float* __restrict__ wq,
    const float* __restrict__ wk,
    const float* __restrict__ wv)
{
    const int chunk = blockIdx.x;
    const int m3    = blockIdx.y;
    const float* w = (m3 == 0) ? wq : (m3 == 1) ? wk : wv;
    unsigned short* dst_hi = g_wt_hi[m3][chunk];
    unsigned short* dst_lo = g_wt_lo[m3][chunk];
    const int tid = threadIdx.x;

    for (int e = 0; e < 16; e++) {
        int p  = e * 128 + tid;
        int h  = p >> 5;
        int kk = (p & 31) * 2;
        float v0 = w[(size_t)(chunk * 64 + kk)     * H_DIM + h];
        float v1 = w[(size_t)(chunk * 64 + kk + 1) * H_DIM + h];
        uint32_t hp, lp;
        split2(v0, v1, hp, lp);
        *(uint32_t*)&dst_hi[h * WT_STRIDE + kk] = hp;
        *(uint32_t*)&dst_lo[h * WT_STRIDE + kk] = lp;
    }
}

// ---------------------------------------------------------------------------
// Projection via mma.sync, pipelined. BM=128 rows/CTA, 384 threads (12 warps).
// Warp w: matrix m3 = w/4, two 16-row strips (w%4)*16 and (w%4)*16+64 of the
// SAME matrix -> B fragments shared across both strips.
// Pipeline per 64-k chunk:
//   - split prefetched A regs -> smem (hi/lo, stride 72)
//   - LDG next chunk's raw A -> regs
//   - cp.async next chunk's B tiles -> alternate buffer, commit
//   - wait_group 1 (current B resident), barrier, MMA, barrier
// SMEM: A hi/lo 2x18432 @0, B double buffer 2x55296 @36864 -> 147456 B.
// Epilogue stores split-bf16 Q (x0.125), K, and transposed V.
// ---------------------------------------------------------------------------
#define PSM_AHI 0
#define PSM_ALO 18432
#define PSM_B   36864
#define PSM_BUF 55296
#define PROJ_SMEM (36864 + 2 * 55296)   // 147456

__global__ __launch_bounds__(384, 1) void proj_mma_kernel(const float* __restrict__ x)
{
    extern __shared__ unsigned char smem[];
    unsigned short* Ah = (unsigned short*)(smem + PSM_AHI);
    unsigned short* Al = (unsigned short*)(smem + PSM_ALO);
    const uint32_t sb = smem_u32(smem);

    const int tid  = threadIdx.x;
    const int wid  = tid >> 5;
    const int lane = tid & 31;
    const int g    = lane >> 2;
    const int t    = lane & 3;
    const int m3   = wid >> 2;            // matrix 0..2
    const int s0   = (wid & 3) * 16;      // strip A row base
    const int s1   = s0 + 64;             // strip B row base
    const int m0   = blockIdx.x * 128;

    float d0[8][4] = {};
    float d1[8][4] = {};
    float2 areg[11];

    // ---- Prologue: B_0 via cp.async, A_0 raw into regs ----
    {
        for (int p = tid; p < 3456; p += 384) {       // uint4 units, 9/thread
            int tile = p / 576;
            int i    = p - tile * 576;
            int tm   = tile >> 1;
            const unsigned short* src = (tile & 1) ? g_wt_lo[tm][0] : g_wt_hi[tm][0];
            cp_async16(sb + PSM_B + tile * 9216 + i * 16, src + i * 8);
        }
        CP_COMMIT();
        #pragma unroll
        for (int e = 0; e < 11; e++) {
            int p = e * 384 + tid;
            if (p < 4096) {
                int r = p >> 5, c = (p & 31) * 2;
                areg[e] = *(const float2*)&x[(size_t)(m0 + r) * C_DIM + c];
            }
        }
    }

    for (int chunk = 0; chunk < 16; chunk++) {
        // ---- Split prefetched A into smem ----
        #pragma unroll
        for (int e = 0; e < 11; e++) {
            int p = e * 384 + tid;
            if (p < 4096) {
                int r = p >> 5, c = (p & 31) * 2;
                uint32_t hp, lp;
                split2(areg[e].x, areg[e].y, hp, lp);
                *(uint32_t*)&Ah[r * WT_STRIDE + c] = hp;
                *(uint32_t*)&Al[r * WT_STRIDE + c] = lp;
            }
        }

        if (chunk < 15) {
            const int kn = (chunk + 1) * 64;
            // Prefetch next A raw
            #pragma unroll
            for (int e = 0; e < 11; e++) {
                int p = e * 384 + tid;
                if (p < 4096) {
                    int r = p >> 5, c = (p & 31) * 2;
                    areg[e] = *(const float2*)&x[(size_t)(m0 + r) * C_DIM + kn + c];
                }
            }
            // Next B via cp.async into alternate buffer
            const uint32_t bufn = sb + PSM_B + ((chunk + 1) & 1) * PSM_BUF;
            for (int p = tid; p < 3456; p += 384) {
                int tile = p / 576;
                int i    = p - tile * 576;
                int tm   = tile >> 1;
                const unsigned short* src = (tile & 1) ? g_wt_lo[tm][chunk + 1]
                                                       : g_wt_hi[tm][chunk + 1];
                cp_async16(bufn + tile * 9216 + i * 16, src + i * 8);
            }
            CP_COMMIT();
            CP_WAIT1();    // current chunk's B group complete
        } else {
            CP_WAIT0();
        }
        __syncthreads();

        // ---- MMAs on current buffer ----
        const unsigned short* Bh = (const unsigned short*)
            (smem + PSM_B + (chunk & 1) * PSM_BUF + (m3 * 2 + 0) * 9216);
        const unsigned short* Bl = (const unsigned short*)
            (smem + PSM_B + (chunk & 1) * PSM_BUF + (m3 * 2 + 1) * 9216);

        #pragma unroll
        for (int ks = 0; ks < 4; ks++) {
            const int ca = ks * 16 + t * 2, cb = ca + 8;
            uint32_t ah0[4], al0[4], ah1[4], al1[4];
            {
                const int ra = s0 + g, rb = s0 + g + 8;
                ah0[0] = *(const uint32_t*)&Ah[ra * WT_STRIDE + ca];
                ah0[1] = *(const uint32_t*)&Ah[rb * WT_STRIDE + ca];
                ah0[2] = *(const uint32_t*)&Ah[ra * WT_STRIDE + cb];
                ah0[3] = *(const uint32_t*)&Ah[rb * WT_STRIDE + cb];
                al0[0] = *(const uint32_t*)&Al[ra * WT_STRIDE + ca];
                al0[1] = *(const uint32_t*)&Al[rb * WT_STRIDE + ca];
                al0[2] = *(const uint32_t*)&Al[ra * WT_STRIDE + cb];
                al0[3] = *(const uint32_t*)&Al[rb * WT_STRIDE + cb];
            }
            {
                const int ra = s1 + g, rb = s1 + g + 8;
                ah1[0] = *(const uint32_t*)&Ah[ra * WT_STRIDE + ca];
                ah1[1] = *(const uint32_t*)&Ah[rb * WT_STRIDE + ca];
                ah1[2] = *(const uint32_t*)&Ah[ra * WT_STRIDE + cb];
                ah1[3] = *(const uint32_t*)&Ah[rb * WT_STRIDE + cb];
                al1[0] = *(const uint32_t*)&Al[ra * WT_STRIDE + ca];
                al1[1] = *(const uint32_t*)&Al[rb * WT_STRIDE + ca];
                al1[2] = *(const uint32_t*)&Al[ra * WT_STRIDE + cb];
                al1[3] = *(const uint32_t*)&Al[rb * WT_STRIDE + cb];
            }
            #pragma unroll
            for (int nt = 0; nt < 8; nt++) {
                const int n = nt * 8 + g;
                uint32_t bh0 = *(const uint32_t*)&Bh[n * WT_STRIDE + ca];
                uint32_t bh1 = *(const uint32_t*)&Bh[n * WT_STRIDE + cb];
                uint32_t bl0 = *(const uint32_t*)&Bl[n * WT_STRIDE + ca];
                uint32_t bl1 = *(const uint32_t*)&Bl[n * WT_STRIDE + cb];
                mma_bf16(d0[nt], ah0, bh0, bh1);
                mma_bf16(d0[nt], ah0, bl0, bl1);
                mma_bf16(d0[nt], al0, bh0, bh1);
                mma_bf16(d1[nt], ah1, bh0, bh1);
                mma_bf16(d1[nt], ah1, bl0, bl1);
                mma_bf16(d1[nt], al1, bh0, bh1);
            }
        }
        __syncthreads();
    }

    // ---- Epilogue: split to bf16 and store (two strips) ----
    #pragma unroll
    for (int sp = 0; sp < 2; sp++) {
        float (*d)[4] = sp ? d1 : d0;
        const int grow0 = m0 + (sp ? s1 : s0) + g;
        if (m3 == 0) {
            #pragma unroll
            for (int nt = 0; nt < 8; nt++) {
                int col = nt * 8 + t * 2;
                uint32_t h0, l0, h1, l1;
                split2(d[nt][0] * 0.125f, d[nt][1] * 0.125f, h0, l0);
                split2(d[nt][2] * 0.125f, d[nt][3] * 0.125f, h1, l1);
                *(uint32_t*)&g_qh[(size_t)grow0 * 64 + col] = h0;
                *(uint32_t*)&g_ql[(size_t)grow0 * 64 + col] = l0;
                *(uint32_t*)&g_qh[(size_t)(grow0 + 8) * 64 + col] = h1;
                *(uint32_t*)&g_ql[(size_t)(grow0 + 8) * 64 + col] = l1;
            }
        } else if (m3 == 1) {
            #pragma unroll
            for (int nt = 0; nt < 8; nt++) {
                int col = nt * 8 + t * 2;
                uint32_t h0, l0, h1, l1;
                split2(d[nt][0], d[nt][1], h0, l0);
                split2(d[nt][2], d[nt][3], h1, l1);
                *(uint32_t*)&g_kh[(size_t)grow0 * 64 + col] = h0;
                *(uint32_t*)&g_kl[(size_t)grow0 * 64 + col] = l0;
                *(uint32_t*)&g_kh[(size_t)(grow0 + 8) * 64 + col] = h1;
                *(uint32_t*)&g_kl[(size_t)(grow0 + 8) * 64 + col] = l1;
            }
        } else {
            #pragma unroll
            for (int nt = 0; nt < 8; nt++) {
                int col = nt * 8 + t * 2;
                #pragma unroll
                for (int c = 0; c < 4; c++) {
                    int cc = col + (c & 1);
                    int rr = grow0 + (c >> 1) * 8;
                    float v = d[nt][c];
                    __nv_bfloat16 vh = __float2bfloat16(v);
                    float vl = v - __bfloat162float(vh);
                    g_vth[(size_t)cc * M_ROWS + rr] = __bfloat16_as_ushort(vh);
                    g_vtl[(size_t)cc * M_ROWS + rr] =
                        __bfloat16_as_ushort(__float2bfloat16(vl));
                }
            }
        }
    }
}

// ---------------------------------------------------------------------------
// Flash attention on mma.sync — UNCHANGED from Round 8 (passed, ~113 us).
// ---------------------------------------------------------------------------
#define ATT_SMEM (4 * 64 * 72 * 2)   // 36864

__global__ __launch_bounds__(128, 3) void attn_mma_kernel(float* __restrict__ out)
{
    extern __shared__ unsigned short smA[];
    unsigned short* Kh = smA;             // [key][h] stride 72
    unsigned short* Kl = smA + 4608;
    unsigned short* Vh = smA + 9216;      // [h][s] stride 72
    unsigned short* Vl = smA + 13824;

    const int tid  = threadIdx.x;
    const int warp = tid >> 5;
    const int lane = tid & 31;
    const int g    = lane >> 2;
    const int t    = lane & 3;
    const int b    = blockIdx.y;
    const int qt   = gridDim.x - 1 - blockIdx.x;   // heavy tiles first
    const int q0   = qt * 64;
    const int mrow = warp * 16;
    const size_t mb = (size_t)b * T_SEQ;

    uint32_t qh[4][4], ql[4][4];
    {
        const int r0 = q0 + mrow + g;
        #pragma unroll
        for (int ks = 0; ks < 4; ks++) {
            const size_t o0 = (mb + r0) * 64 + ks * 16 + 2 * t;
            const size_t o1 = o0 + 8 * 64;
            qh[ks][0] = *(const uint32_t*)&g_qh[o0];
            qh[ks][1] = *(const uint32_t*)&g_qh[o1];
            qh[ks][2] = *(const uint32_t*)&g_qh[o0 + 8];
            qh[ks][3] = *(const uint32_t*)&g_qh[o1 + 8];
            ql[ks][0] = *(const uint32_t*)&g_ql[o0];
            ql[ks][1] = *(const uint32_t*)&g_ql[o1];
            ql[ks][2] = *(const uint32_t*)&g_ql[o0 + 8];
            ql[ks][3] = *(const uint32_t*)&g_ql[o1 + 8];
        }
    }

    float o[8][4] = {};
    float m_r[2] = {-1e30f, -1e30f};
    float l_r[2] = {0.0f, 0.0f};

    for (int j0 = 0; j0 <= q0; j0 += 64) {
        #pragma unroll
        for (int e = 0; e < 16; e++) {
            int p    = e * 128 + tid;
            int tile = p >> 9;
            int i    = p & 511;
            int row  = i >> 3;
            int c8   = i & 7;
            const unsigned short* src;
            if (tile == 0)      src = &g_kh[(mb + j0 + row) * 64 + c8 * 8];
            else if (tile == 1) src = &g_kl[(mb + j0 + row) * 64 + c8 * 8];
            else if (tile == 2) src = &g_vth[(size_t)row * M_ROWS + mb + j0 + c8 * 8];
            else                src = &g_vtl[(size_t)row * M_ROWS + mb + j0 + c8 * 8];
            *(uint4*)&smA[tile * 4608 + row * 72 + c8 * 8] = *(const uint4*)src;
        }
        __syncthreads();

        float s[8][4] = {};
        #pragma unroll
        for (int ks = 0; ks < 4; ks++) {
            const int ca = ks * 16 + 2 * t, cb = ca + 8;
            #pragma unroll
            for (int nt = 0; nt < 8; nt++) {
                const int n = nt * 8 + g;
                uint32_t bh0 = *(const uint32_t*)&Kh[n * 72 + ca];
                uint32_t bh1 = *(const uint32_t*)&Kh[n * 72 + cb];
                uint32_t bl0 = *(const uint32_t*)&Kl[n * 72 + ca];
                uint32_t bl1 = *(const uint32_t*)&Kl[n * 72 + cb];
                mma_bf16(s[nt], qh[ks], bh0, bh1);
                mma_bf16(s[nt], qh[ks], bl0, bl1);
                mma_bf16(s[nt], ql[ks], bh0, bh1);
            }
        }

        if (j0 == q0) {
            #pragma unroll
            for (int nt = 0; nt < 8; nt++) {
                #pragma unroll
                for (int c = 0; c < 4; c++) {
                    int col = nt * 8 + 2 * t + (c & 1);
                    int row = mrow + g + (c >> 1) * 8;
                    if (col > row) s[nt][c] = -1e30f;
                }
            }
        }

        float mt0 = -1e30f, mt1 = -1e30f;
        #pragma unroll
        for (int nt = 0; nt < 8; nt++) {
            mt0 = fmaxf(mt0, fmaxf(s[nt][0], s[nt][1]));
            mt1 = fmaxf(mt1, fmaxf(s[nt][2], s[nt][3]));
        }
        mt0 = fmaxf(mt0, __shfl_xor_sync(0xffffffffu, mt0, 1));
        mt0 = fmaxf(mt0, __shfl_xor_sync(0xffffffffu, mt0, 2));
        mt1 = fmaxf(mt1, __shfl_xor_sync(0xffffffffu, mt1, 1));
        mt1 = fmaxf(mt1, __shfl_xor_sync(0xffffffffu, mt1, 2));

        float mn0 = fmaxf(m_r[0], mt0);
        float mn1 = fmaxf(m_r[1], mt1);
        float a0 = __expf(m_r[0] - mn0);
        float a1 = __expf(m_r[1] - mn1);
        m_r[0] = mn0; m_r[1] = mn1;

        float rs0 = 0.0f, rs1 = 0.0f;
        #pragma unroll
        for (int nt = 0; nt < 8; nt++) {
            s[nt][0] = __expf(s[nt][0] - mn0);
            s[nt][1] = __expf(s[nt][1] - mn0);
            s[nt][2] = __expf(s[nt][2] - mn1);
            s[nt][3] = __expf(s[nt][3] - mn1);
            rs0 += s[nt][0] + s[nt][1];
            rs1 += s[nt][2] + s[nt][3];
        }
        rs0 += __shfl_xor_sync(0xffffffffu, rs0, 1);
        rs0 += __shfl_xor_sync(0xffffffffu, rs0, 2);
        rs1 += __shfl_xor_sync(0xffffffffu, rs1, 1);
        rs1 += __shfl_xor_sync(0xffffffffu, rs1, 2);
        l_r[0] = l_r[0] * a0 + rs0;
        l_r[1] = l_r[1] * a1 + rs1;

        #pragma unroll
        for (int nt = 0; nt < 8; nt++) {
            o[nt][0] *= a0; o[nt][1] *= a0;
            o[nt][2] *= a1; o[nt][3] *= a1;
        }

        #pragma unroll
        for (int ks = 0; ks < 4; ks++) {
            uint32_t ph[4], pl[4];
            const int n0 = 2 * ks, n1 = 2 * ks + 1;
            ph[0] = bpack(s[n0][0], s[n0][1]);
            ph[1] = bpack(s[n0][2], s[n0][3]);
            ph[2] = bpack(s[n1][0], s[n1][1]);
            ph[3] = bpack(s[n1][2], s[n1][3]);
            pl[0] = bpack(bf_lo(s[n0][0]), bf_lo(s[n0][1]));
            pl[1] = bpack(bf_lo(s[n0][2]), bf_lo(s[n0][3]));
            pl[2] = bpack(bf_lo(s[n1][0]), bf_lo(s[n1][1]));
            pl[3] = bpack(bf_lo(s[n1][2]), bf_lo(s[n1][3]));
            const int ca = ks * 16 + 2 * t, cb = ca + 8;
            #pragma unroll
            for (int nt = 0; nt < 8; nt++) {
                const int n = nt * 8 + g;
                uint32_t bh0 = *(const uint32_t*)&Vh[n * 72 + ca];
                uint32_t bh1 = *(const uint32_t*)&Vh[n * 72 + cb];
                uint32_t bl0 = *(const uint32_t*)&Vl[n * 72 + ca];
                uint32_t bl1 = *(const uint32_t*)&Vl[n * 72 + cb];
                mma_bf16(o[nt], ph, bh0, bh1);
                mma_bf16(o[nt], ph, bl0, bl1);
                mma_bf16(o[nt], pl, bh0, bh1);
            }
        }
        __syncthreads();
    }

    const float inv0 = 1.0f / l_r[0];
    const float inv1 = 1.0f / l_r[1];
    const size_t r0 = mb + q0 + mrow + g;
    #pragma unroll
    for (int nt = 0; nt < 8; nt++) {
        const int col = nt * 8 + 2 * t;
        *(float2*)&out[r0 * 64 + col] =
            make_float2(o[nt][0] * inv0, o[nt][1] * inv0);
        *(float2*)&out[(r0 + 8) * 64 + col] =
            make_float2(o[nt][2] * inv1, o[nt][3] * inv1);
    }
}

// ---------------------------------------------------------------------------
extern "C" void kernel_launch(void* const* d_in, const int* in_sizes, int n_in,
                              void* d_out, int out_size)
{
    const float* x  = (const float*)d_in[0];
    const float* wq = (const float*)d_in[1];
    const float* wk = (const float*)d_in[2];
    const float* wv = (const float*)d_in[3];
    float* out = (float*)d_out;

    (void)in_sizes; (void)n_in; (void)out_size;

    cudaFuncSetAttribute(proj_mma_kernel,
                         cudaFuncAttributeMaxDynamicSharedMemorySize, PROJ_SMEM);
    cudaFuncSetAttribute(attn_mma_kernel,
                         cudaFuncAttributeMaxDynamicSharedMemorySize, ATT_SMEM);

    // 1) Prep transposed/split/padded weights (tiny)
    wprep_kernel<<<dim3(16, 3), 128>>>(wq, wk, wv);

    // 2) QKV projection, pipelined mma.sync (BM=128)
    proj_mma_kernel<<<M_ROWS / 128, 384, PROJ_SMEM>>>(x);

    // 3) Attention on mma.sync: grid (32 q-tiles reversed, 16 batches)
    attn_mma_kernel<<<dim3(T_SEQ / 64, B_DIM), 128, ATT_SMEM>>>(out);
}

// round 11
// speedup vs baseline: 5.9529x; 1.1933x over previous
#include <cuda_runtime.h>
#include <cuda_bf16.h>
#include <cuda_fp16.h>
#include <stdint.h>

// Problem constants
#define T_SEQ 2048
#define C_DIM 1024
#define H_DIM 64
#define B_DIM 16
#define M_ROWS (B_DIM * T_SEQ)   // 32768

// Q/K stored as split bf16 (value = hi + lo), row-major [m][h].
// Q is pre-scaled by 1/sqrt(H) = 0.125. V stored TRANSPOSED [h][m] as fp16.
__device__ unsigned short g_qh[M_ROWS * H_DIM];
__device__ unsigned short g_ql[M_ROWS * H_DIM];
__device__ unsigned short g_kh[M_ROWS * H_DIM];
__device__ unsigned short g_kl[M_ROWS * H_DIM];
__device__ unsigned short g_vth[H_DIM * M_ROWS];   // fp16

// Pre-transposed (B[n=h][k]), hi/lo-split bf16 weights, padded stride 72.
#define WT_STRIDE 72
__device__ __align__(16) unsigned short g_wt_hi[3][16][64 * WT_STRIDE];
__device__ __align__(16) unsigned short g_wt_lo[3][16][64 * WT_STRIDE];

// ---------------------------------------------------------------------------
// Warp-level MMAs (standard PTX; bf16 variant validated R7-R9).
// Fragment maps (g=lane>>2, t=lane&3):
//   A: a0=(g,2t) a1=(g+8,2t) a2=(g,2t+8) a3=(g+8,2t+8)   [pairs k,k+1]
//   B: b0=(k=2t,n=g) b1=(k=2t+8,n=g)
//   D: c0,c1=(g,2t..2t+1) c2,c3=(g+8,2t..2t+1)
// ---------------------------------------------------------------------------
__device__ __forceinline__ void mma_bf16(float* d, const uint32_t* a,
                                         uint32_t b0, uint32_t b1) {
    asm volatile(
        "mma.sync.aligned.m16n8k16.row.col.f32.bf16.bf16.f32 "
        "{%0,%1,%2,%3}, {%4,%5,%6,%7}, {%8,%9}, {%0,%1,%2,%3};"
        : "+f"(d[0]), "+f"(d[1]), "+f"(d[2]), "+f"(d[3])
        : "r"(a[0]), "r"(a[1]), "r"(a[2]), "r"(a[3]), "r"(b0), "r"(b1));
}

__device__ __forceinline__ void mma_fp16(float* d, const uint32_t* a,
                                         uint32_t b0, uint32_t b1) {
    asm volatile(
        "mma.sync.aligned.m16n8k16.row.col.f32.f16.f16.f32 "
        "{%0,%1,%2,%3}, {%4,%5,%6,%7}, {%8,%9}, {%0,%1,%2,%3};"
        : "+f"(d[0]), "+f"(d[1]), "+f"(d[2]), "+f"(d[3])
        : "r"(a[0]), "r"(a[1]), "r"(a[2]), "r"(a[3]), "r"(b0), "r"(b1));
}

__device__ __forceinline__ void split2(float a, float b, uint32_t& hi, uint32_t& lo) {
    __nv_bfloat16 ah = __float2bfloat16(a), bh = __float2bfloat16(b);
    __nv_bfloat16 al = __float2bfloat16(a - __bfloat162float(ah));
    __nv_bfloat16 bl = __float2bfloat16(b - __bfloat162float(bh));
    hi = ((uint32_t)__bfloat16_as_ushort(bh) << 16) | __bfloat16_as_ushort(ah);
    lo = ((uint32_t)__bfloat16_as_ushort(bl) << 16) | __bfloat16_as_ushort(al);
}

__device__ __forceinline__ uint32_t hpack(float a, float b) {
    __half2 h = __floats2half2_rn(a, b);
    return *(uint32_t*)&h;
}

__device__ __forceinline__ uint32_t smem_u32(const void* p) {
    uint32_t a;
    asm("{ .reg .u64 t; cvta.to.shared.u64 t, %1; cvt.u32.u64 %0, t; }"
        : "=r"(a) : "l"(p));
    return a;
}

__device__ __forceinline__ void cp_async16(uint32_t smem_dst, const void* gmem_src) {
    asm volatile("cp.async.cg.shared.global [%0], [%1], 16;"
                 :: "r"(smem_dst), "l"(gmem_src));
}
#define CP_COMMIT()  asm volatile("cp.async.commit_group;")
#define CP_WAIT1()   asm volatile("cp.async.wait_group 1;")
#define CP_WAIT0()   asm volatile("cp.async.wait_group 0;")

// ---------------------------------------------------------------------------
// Weight prep: w[k][h] -> B[n=h][k] col-major, hi/lo split, stride 72.
// ---------------------------------------------------------------------------
__global__ __launch_bounds__(128) void wprep_kernel(
    const float* __restrict__ wq,
    const float* __restrict__ wk,
    const float* __restrict__ wv)
{
    const int chunk = blockIdx.x;
    const int m3    = blockIdx.y;
    const float* w = (m3 == 0) ? wq : (m3 == 1) ? wk : wv;
    unsigned short* dst_hi = g_wt_hi[m3][chunk];
    unsigned short* dst_lo = g_wt_lo[m3][chunk];
    const int tid = threadIdx.x;

    for (int e = 0; e < 16; e++) {
        int p  = e * 128 + tid;
        int h  = p >> 5;
        int kk = (p & 31) * 2;
        float v0 = w[(size_t)(chunk * 64 + kk)     * H_DIM + h];
        float v1 = w[(size_t)(chunk * 64 + kk + 1) * H_DIM + h];
        uint32_t hp, lp;
        split2(v0, v1, hp, lp);
        *(uint32_t*)&dst_hi[h * WT_STRIDE + kk] = hp;
        *(uint32_t*)&dst_lo[h * WT_STRIDE + kk] = lp;
    }
}

// ---------------------------------------------------------------------------
// Projection via mma.sync, pipelined (unchanged from R9 except V epilogue
// stores single fp16 transposed).
// ---------------------------------------------------------------------------
#define PSM_AHI 0
#define PSM_ALO 18432
#define PSM_B   36864
#define PSM_BUF 55296
#define PROJ_SMEM (36864 + 2 * 55296)   // 147456

__global__ __launch_bounds__(384, 1) void proj_mma_kernel(const float* __restrict__ x)
{
    extern __shared__ unsigned char smem[];
    unsigned short* Ah = (unsigned short*)(smem + PSM_AHI);
    unsigned short* Al = (unsigned short*)(smem + PSM_ALO);
    const uint32_t sb = smem_u32(smem);

    const int tid  = threadIdx.x;
    const int wid  = tid >> 5;
    const int lane = tid & 31;
    const int g    = lane >> 2;
    const int t    = lane & 3;
    const int m3   = wid >> 2;
    const int s0   = (wid & 3) * 16;
    const int s1   = s0 + 64;
    const int m0   = blockIdx.x * 128;

    float d0[8][4] = {};
    float d1[8][4] = {};
    float2 areg[11];

    {
        for (int p = tid; p < 3456; p += 384) {
            int tile = p / 576;
            int i    = p - tile * 576;
            int tm   = tile >> 1;
            const unsigned short* src = (tile & 1) ? g_wt_lo[tm][0] : g_wt_hi[tm][0];
            cp_async16(sb + PSM_B + tile * 9216 + i * 16, src + i * 8);
        }
        CP_COMMIT();
        #pragma unroll
        for (int e = 0; e < 11; e++) {
            int p = e * 384 + tid;
            if (p < 4096) {
                int r = p >> 5, c = (p & 31) * 2;
                areg[e] = *(const float2*)&x[(size_t)(m0 + r) * C_DIM + c];
            }
        }
    }

    for (int chunk = 0; chunk < 16; chunk++) {
        #pragma unroll
        for (int e = 0; e < 11; e++) {
            int p = e * 384 + tid;
            if (p < 4096) {
                int r = p >> 5, c = (p & 31) * 2;
                uint32_t hp, lp;
                split2(areg[e].x, areg[e].y, hp, lp);
                *(uint32_t*)&Ah[r * WT_STRIDE + c] = hp;
                *(uint32_t*)&Al[r * WT_STRIDE + c] = lp;
            }
        }

        if (chunk < 15) {
            const int kn = (chunk + 1) * 64;
            #pragma unroll
            for (int e = 0; e < 11; e++) {
                int p = e * 384 + tid;
                if (p < 4096) {
                    int r = p >> 5, c = (p & 31) * 2;
                    areg[e] = *(const float2*)&x[(size_t)(m0 + r) * C_DIM + kn + c];
                }
            }
            const uint32_t bufn = sb + PSM_B + ((chunk + 1) & 1) * PSM_BUF;
            for (int p = tid; p < 3456; p += 384) {
                int tile = p / 576;
                int i    = p - tile * 576;
                int tm   = tile >> 1;
                const unsigned short* src = (tile & 1) ? g_wt_lo[tm][chunk + 1]
                                                       : g_wt_hi[tm][chunk + 1];
                cp_async16(bufn + tile * 9216 + i * 16, src + i * 8);
            }
            CP_COMMIT();
            CP_WAIT1();
        } else {
            CP_WAIT0();
        }
        __syncthreads();

        const unsigned short* Bh = (const unsigned short*)
            (smem + PSM_B + (chunk & 1) * PSM_BUF + (m3 * 2 + 0) * 9216);
        const unsigned short* Bl = (const unsigned short*)
            (smem + PSM_B + (chunk & 1) * PSM_BUF + (m3 * 2 + 1) * 9216);

        #pragma unroll
        for (int ks = 0; ks < 4; ks++) {
            const int ca = ks * 16 + t * 2, cb = ca + 8;
            uint32_t ah0[4], al0[4], ah1[4], al1[4];
            {
                const int ra = s0 + g, rb = s0 + g + 8;
                ah0[0] = *(const uint32_t*)&Ah[ra * WT_STRIDE + ca];
                ah0[1] = *(const uint32_t*)&Ah[rb * WT_STRIDE + ca];
                ah0[2] = *(const uint32_t*)&Ah[ra * WT_STRIDE + cb];
                ah0[3] = *(const uint32_t*)&Ah[rb * WT_STRIDE + cb];
                al0[0] = *(const uint32_t*)&Al[ra * WT_STRIDE + ca];
                al0[1] = *(const uint32_t*)&Al[rb * WT_STRIDE + ca];
                al0[2] = *(const uint32_t*)&Al[ra * WT_STRIDE + cb];
                al0[3] = *(const uint32_t*)&Al[rb * WT_STRIDE + cb];
            }
            {
                const int ra = s1 + g, rb = s1 + g + 8;
                ah1[0] = *(const uint32_t*)&Ah[ra * WT_STRIDE + ca];
                ah1[1] = *(const uint32_t*)&Ah[rb * WT_STRIDE + ca];
                ah1[2] = *(const uint32_t*)&Ah[ra * WT_STRIDE + cb];
                ah1[3] = *(const uint32_t*)&Ah[rb * WT_STRIDE + cb];
                al1[0] = *(const uint32_t*)&Al[ra * WT_STRIDE + ca];
                al1[1] = *(const uint32_t*)&Al[rb * WT_STRIDE + ca];
                al1[2] = *(const uint32_t*)&Al[ra * WT_STRIDE + cb];
                al1[3] = *(const uint32_t*)&Al[rb * WT_STRIDE + cb];
            }
            #pragma unroll
            for (int nt = 0; nt < 8; nt++) {
                const int n = nt * 8 + g;
                uint32_t bh0 = *(const uint32_t*)&Bh[n * WT_STRIDE + ca];
                uint32_t bh1 = *(const uint32_t*)&Bh[n * WT_STRIDE + cb];
                uint32_t bl0 = *(const uint32_t*)&Bl[n * WT_STRIDE + ca];
                uint32_t bl1 = *(const uint32_t*)&Bl[n * WT_STRIDE + cb];
                mma_bf16(d0[nt], ah0, bh0, bh1);
                mma_bf16(d0[nt], ah0, bl0, bl1);
                mma_bf16(d0[nt], al0, bh0, bh1);
                mma_bf16(d1[nt], ah1, bh0, bh1);
                mma_bf16(d1[nt], ah1, bl0, bl1);
                mma_bf16(d1[nt], al1, bh0, bh1);
            }
        }
        __syncthreads();
    }

    #pragma unroll
    for (int sp = 0; sp < 2; sp++) {
        float (*d)[4] = sp ? d1 : d0;
        const int grow0 = m0 + (sp ? s1 : s0) + g;
        if (m3 == 0) {
            #pragma unroll
            for (int nt = 0; nt < 8; nt++) {
                int col = nt * 8 + t * 2;
                uint32_t h0, l0, h1, l1;
                split2(d[nt][0] * 0.125f, d[nt][1] * 0.125f, h0, l0);
                split2(d[nt][2] * 0.125f, d[nt][3] * 0.125f, h1, l1);
                *(uint32_t*)&g_qh[(size_t)grow0 * 64 + col] = h0;
                *(uint32_t*)&g_ql[(size_t)grow0 * 64 + col] = l0;
                *(uint32_t*)&g_qh[(size_t)(grow0 + 8) * 64 + col] = h1;
                *(uint32_t*)&g_ql[(size_t)(grow0 + 8) * 64 + col] = l1;
            }
        } else if (m3 == 1) {
            #pragma unroll
            for (int nt = 0; nt < 8; nt++) {
                int col = nt * 8 + t * 2;
                uint32_t h0, l0, h1, l1;
                split2(d[nt][0], d[nt][1], h0, l0);
                split2(d[nt][2], d[nt][3], h1, l1);
                *(uint32_t*)&g_kh[(size_t)grow0 * 64 + col] = h0;
                *(uint32_t*)&g_kl[(size_t)grow0 * 64 + col] = l0;
                *(uint32_t*)&g_kh[(size_t)(grow0 + 8) * 64 + col] = h1;
                *(uint32_t*)&g_kl[(size_t)(grow0 + 8) * 64 + col] = l1;
            }
        } else {
            // V: single fp16, transposed [h][m]
            #pragma unroll
            for (int nt = 0; nt < 8; nt++) {
                int col = nt * 8 + t * 2;
                #pragma unroll
                for (int c = 0; c < 4; c++) {
                    int cc = col + (c & 1);
                    int rr = grow0 + (c >> 1) * 8;
                    __half vh = __float2half_rn(d[nt][c]);
                    g_vth[(size_t)cc * M_ROWS + rr] = *(unsigned short*)&vh;
                }
            }
        }
    }
}

// ---------------------------------------------------------------------------
// Flash attention on mma.sync, Round-10 version:
//  - PV phase: single fp16 MMA (P and V in fp16; l stays exact fp32).
//  - K hi/lo + V staging via cp.async, double buffered: next tile streams in
//    while current tile's MMAs run.
// CTA: 128 threads, BQ=64. Smem: 2 buffers x (Kh,Kl,V) x 4608 shorts = 55296B.
// Grid (32 reversed q-tiles, 16 batches).
// ---------------------------------------------------------------------------
#define ATT_TILE  4608                 // shorts per sub-tile (64 x 72)
#define ATT_BUF   (3 * ATT_TILE)       // shorts per buffer
#define ATT_SMEM  (2 * ATT_BUF * 2)    // bytes = 55296

__global__ __launch_bounds__(128, 3) void attn_mma_kernel(float* __restrict__ out)
{
    extern __shared__ unsigned short smA[];
    const uint32_t sb = smem_u32(smA);

    const int tid  = threadIdx.x;
    const int warp = tid >> 5;
    const int lane = tid & 31;
    const int g    = lane >> 2;
    const int t    = lane & 3;
    const int b    = blockIdx.y;
    const int qt   = gridDim.x - 1 - blockIdx.x;   // heavy tiles first
    const int q0   = qt * 64;
    const int mrow = warp * 16;
    const size_t mb = (size_t)b * T_SEQ;

    // Per-thread staging coords: 12 cp.async of 16B per tile
    // p = e*128 + tid, tile = p>>9 (0..2), i = p&511, row = i>>3, c8 = i&7.

    // ---- Prologue: stage tile j0=0 into buffer 0 ----
    #pragma unroll
    for (int e = 0; e < 12; e++) {
        int p    = e * 128 + tid;
        int tile = p >> 9;
        int i    = p & 511;
        int row  = i >> 3;
        int c8   = i & 7;
        const unsigned short* src;
        if (tile == 0)      src = &g_kh[(mb + row) * 64 + c8 * 8];
        else if (tile == 1) src = &g_kl[(mb + row) * 64 + c8 * 8];
        else                src = &g_vth[(size_t)row * M_ROWS + mb + c8 * 8];
        cp_async16(sb + (tile * ATT_TILE + row * 72 + c8 * 8) * 2, src);
    }
    CP_COMMIT();

    // ---- Q fragments (loop-invariant) ----
    uint32_t qh[4][4], ql[4][4];
    {
        const int r0 = q0 + mrow + g;
        #pragma unroll
        for (int ks = 0; ks < 4; ks++) {
            const size_t o0 = (mb + r0) * 64 + ks * 16 + 2 * t;
            const size_t o1 = o0 + 8 * 64;
            qh[ks][0] = *(const uint32_t*)&g_qh[o0];
            qh[ks][1] = *(const uint32_t*)&g_qh[o1];
            qh[ks][2] = *(const uint32_t*)&g_qh[o0 + 8];
            qh[ks][3] = *(const uint32_t*)&g_qh[o1 + 8];
            ql[ks][0] = *(const uint32_t*)&g_ql[o0];
            ql[ks][1] = *(const uint32_t*)&g_ql[o1];
            ql[ks][2] = *(const uint32_t*)&g_ql[o0 + 8];
            ql[ks][3] = *(const uint32_t*)&g_ql[o1 + 8];
        }
    }

    float o[8][4] = {};
    float m_r[2] = {-1e30f, -1e30f};
    float l_r[2] = {0.0f, 0.0f};

    for (int j0 = 0; j0 <= q0; j0 += 64) {
        const int cur = (j0 >> 6) & 1;

        // ---- Stage next tile into alternate buffer, then wait for current ----
        if (j0 + 64 <= q0) {
            const int jn = j0 + 64;
            const uint32_t bufn = sb + ((cur ^ 1) * ATT_BUF) * 2;
            #pragma unroll
            for (int e = 0; e < 12; e++) {
                int p    = e * 128 + tid;
                int tile = p >> 9;
                int i    = p & 511;
                int row  = i >> 3;
                int c8   = i & 7;
                const unsigned short* src;
                if (tile == 0)      src = &g_kh[(mb + jn + row) * 64 + c8 * 8];
                else if (tile == 1) src = &g_kl[(mb + jn + row) * 64 + c8 * 8];
                else                src = &g_vth[(size_t)row * M_ROWS + mb + jn + c8 * 8];
                cp_async16(bufn + (tile * ATT_TILE + row * 72 + c8 * 8) * 2, src);
            }
            CP_COMMIT();
            CP_WAIT1();
        } else {
            CP_WAIT0();
        }
        __syncthreads();

        const unsigned short* Kh = smA + cur * ATT_BUF;
        const unsigned short* Kl = Kh + ATT_TILE;
        const unsigned short* Vh = Kh + 2 * ATT_TILE;

        // ---- S = Q K^T (3-term bf16 split) ----
        float s[8][4] = {};
        #pragma unroll
        for (int ks = 0; ks < 4; ks++) {
            const int ca = ks * 16 + 2 * t, cb = ca + 8;
            #pragma unroll
            for (int nt = 0; nt < 8; nt++) {
                const int n = nt * 8 + g;
                uint32_t bh0 = *(const uint32_t*)&Kh[n * 72 + ca];
                uint32_t bh1 = *(const uint32_t*)&Kh[n * 72 + cb];
                uint32_t bl0 = *(const uint32_t*)&Kl[n * 72 + ca];
                uint32_t bl1 = *(const uint32_t*)&Kl[n * 72 + cb];
                mma_bf16(s[nt], qh[ks], bh0, bh1);
                mma_bf16(s[nt], qh[ks], bl0, bl1);
                mma_bf16(s[nt], ql[ks], bh0, bh1);
            }
        }

        // ---- Causal mask (diagonal tile only) ----
        if (j0 == q0) {
            #pragma unroll
            for (int nt = 0; nt < 8; nt++) {
                #pragma unroll
                for (int c = 0; c < 4; c++) {
                    int col = nt * 8 + 2 * t + (c & 1);
                    int row = mrow + g + (c >> 1) * 8;
                    if (col > row) s[nt][c] = -1e30f;
                }
            }
        }

        // ---- Online softmax ----
        float mt0 = -1e30f, mt1 = -1e30f;
        #pragma unroll
        for (int nt = 0; nt < 8; nt++) {
            mt0 = fmaxf(mt0, fmaxf(s[nt][0], s[nt][1]));
            mt1 = fmaxf(mt1, fmaxf(s[nt][2], s[nt][3]));
        }
        mt0 = fmaxf(mt0, __shfl_xor_sync(0xffffffffu, mt0, 1));
        mt0 = fmaxf(mt0, __shfl_xor_sync(0xffffffffu, mt0, 2));
        mt1 = fmaxf(mt1, __shfl_xor_sync(0xffffffffu, mt1, 1));
        mt1 = fmaxf(mt1, __shfl_xor_sync(0xffffffffu, mt1, 2));

        float mn0 = fmaxf(m_r[0], mt0);
        float mn1 = fmaxf(m_r[1], mt1);
        float a0 = __expf(m_r[0] - mn0);
        float a1 = __expf(m_r[1] - mn1);
        m_r[0] = mn0; m_r[1] = mn1;

        float rs0 = 0.0f, rs1 = 0.0f;
        #pragma unroll
        for (int nt = 0; nt < 8; nt++) {
            s[nt][0] = __expf(s[nt][0] - mn0);
            s[nt][1] = __expf(s[nt][1] - mn0);
            s[nt][2] = __expf(s[nt][2] - mn1);
            s[nt][3] = __expf(s[nt][3] - mn1);
            rs0 += s[nt][0] + s[nt][1];
            rs1 += s[nt][2] + s[nt][3];
        }
        rs0 += __shfl_xor_sync(0xffffffffu, rs0, 1);
        rs0 += __shfl_xor_sync(0xffffffffu, rs0, 2);
        rs1 += __shfl_xor_sync(0xffffffffu, rs1, 1);
        rs1 += __shfl_xor_sync(0xffffffffu, rs1, 2);
        l_r[0] = l_r[0] * a0 + rs0;
        l_r[1] = l_r[1] * a1 + rs1;

        #pragma unroll
        for (int nt = 0; nt < 8; nt++) {
            o[nt][0] *= a0; o[nt][1] *= a0;
            o[nt][2] *= a1; o[nt][3] *= a1;
        }

        // ---- O += P V  (single fp16 MMA per (ks, nt)) ----
        #pragma unroll
        for (int ks = 0; ks < 4; ks++) {
            uint32_t ph[4];
            const int n0 = 2 * ks, n1 = 2 * ks + 1;
            ph[0] = hpack(s[n0][0], s[n0][1]);
            ph[1] = hpack(s[n0][2], s[n0][3]);
            ph[2] = hpack(s[n1][0], s[n1][1]);
            ph[3] = hpack(s[n1][2], s[n1][3]);
            const int ca = ks * 16 + 2 * t, cb = ca + 8;
            #pragma unroll
            for (int nt = 0; nt < 8; nt++) {
                const int n = nt * 8 + g;
                uint32_t b0 = *(const uint32_t*)&Vh[n * 72 + ca];
                uint32_t b1 = *(const uint32_t*)&Vh[n * 72 + cb];
                mma_fp16(o[nt], ph, b0, b1);
            }
        }
        __syncthreads();   // all reads of cur buffer done before it's re-staged
    }

    // ---- Finalize ----
    const float inv0 = 1.0f / l_r[0];
    const float inv1 = 1.0f / l_r[1];
    const size_t r0 = mb + q0 + mrow + g;
    #pragma unroll
    for (int nt = 0; nt < 8; nt++) {
        const int col = nt * 8 + 2 * t;
        *(float2*)&out[r0 * 64 + col] =
            make_float2(o[nt][0] * inv0, o[nt][1] * inv0);
        *(float2*)&out[(r0 + 8) * 64 + col] =
            make_float2(o[nt][2] * inv1, o[nt][3] * inv1);
    }
}

// ---------------------------------------------------------------------------
extern "C" void kernel_launch(void* const* d_in, const int* in_sizes, int n_in,
                              void* d_out, int out_size)
{
    const float* x  = (const float*)d_in[0];
    const float* wq = (const float*)d_in[1];
    const float* wk = (const float*)d_in[2];
    const float* wv = (const float*)d_in[3];
    float* out = (float*)d_out;

    (void)in_sizes; (void)n_in; (void)out_size;

    cudaFuncSetAttribute(proj_mma_kernel,
                         cudaFuncAttributeMaxDynamicSharedMemorySize, PROJ_SMEM);
    cudaFuncSetAttribute(attn_mma_kernel,
                         cudaFuncAttributeMaxDynamicSharedMemorySize, ATT_SMEM);

    // 1) Prep transposed/split/padded weights (tiny)
    wprep_kernel<<<dim3(16, 3), 128>>>(wq, wk, wv);

    // 2) QKV projection, pipelined mma.sync (BM=128)
    proj_mma_kernel<<<M_ROWS / 128, 384, PROJ_SMEM>>>(x);

    // 3) Attention: fp16 PV + cp.async double-buffered staging
    attn_mma_kernel<<<dim3(T_SEQ / 64, B_DIM), 128, ATT_SMEM>>>(out);
}

// round 15
// speedup vs baseline: 6.1195x; 1.0280x over previous
#include <cuda_runtime.h>
#include <cuda_bf16.h>
#include <cuda_fp16.h>
#include <stdint.h>

// Problem constants
#define T_SEQ 2048
#define C_DIM 1024
#define H_DIM 64
#define B_DIM 16
#define M_ROWS (B_DIM * T_SEQ)   // 32768

// Q/K stored as split bf16 (value = hi + lo), row-major [m][h].
// Q is pre-scaled by 1/sqrt(H) = 0.125. V stored TRANSPOSED [h][m] as fp16.
__device__ unsigned short g_qh[M_ROWS * H_DIM];
__device__ unsigned short g_ql[M_ROWS * H_DIM];
__device__ unsigned short g_kh[M_ROWS * H_DIM];
__device__ unsigned short g_kl[M_ROWS * H_DIM];
__device__ unsigned short g_vth[H_DIM * M_ROWS];   // fp16

// Pre-transposed (B[n=h][k]), hi/lo-split bf16 weights, padded stride 72.
#define WT_STRIDE 72
__device__ __align__(16) unsigned short g_wt_hi[3][16][64 * WT_STRIDE];
__device__ __align__(16) unsigned short g_wt_lo[3][16][64 * WT_STRIDE];

// ---------------------------------------------------------------------------
// Warp-level MMAs + ldmatrix (standard PTX; validated R7-R11).
// Fragment maps (g=lane>>2, t=lane&3):
//   A: a0=(g,2t) a1=(g+8,2t) a2=(g,2t+8) a3=(g+8,2t+8)   [pairs k,k+1]
//   B: b0=(k=2t,n=g) b1=(k=2t+8,n=g)
//   D: c0,c1=(g,2t..2t+1) c2,c3=(g+8,2t..2t+1)
// ldmatrix.x4 lane->matrix: lanes 0-7 mat0, 8-15 mat1, 16-23 mat2, 24-31 mat3.
// B loads: mats = (n+0,k+0),(n+0,k+8),(n+8,k+0),(n+8,k+8) -> {b0,b1} x 2 nts.
// A loads: mats = (m+0,k+0),(m+8,k+0),(m+0,k+8),(m+8,k+8) -> {a0,a1,a2,a3}.
// ---------------------------------------------------------------------------
__device__ __forceinline__ void mma_bf16(float* d, const uint32_t* a,
                                         uint32_t b0, uint32_t b1) {
    asm volatile(
        "mma.sync.aligned.m16n8k16.row.col.f32.bf16.bf16.f32 "
        "{%0,%1,%2,%3}, {%4,%5,%6,%7}, {%8,%9}, {%0,%1,%2,%3};"
        : "+f"(d[0]), "+f"(d[1]), "+f"(d[2]), "+f"(d[3])
        : "r"(a[0]), "r"(a[1]), "r"(a[2]), "r"(a[3]), "r"(b0), "r"(b1));
}

__device__ __forceinline__ void mma_fp16(float* d, const uint32_t* a,
                                         uint32_t b0, uint32_t b1) {
    asm volatile(
        "mma.sync.aligned.m16n8k16.row.col.f32.f16.f16.f32 "
        "{%0,%1,%2,%3}, {%4,%5,%6,%7}, {%8,%9}, {%0,%1,%2,%3};"
        : "+f"(d[0]), "+f"(d[1]), "+f"(d[2]), "+f"(d[3])
        : "r"(a[0]), "r"(a[1]), "r"(a[2]), "r"(a[3]), "r"(b0), "r"(b1));
}

__device__ __forceinline__ void ldsm_x4(uint32_t addr, uint32_t& r0, uint32_t& r1,
                                        uint32_t& r2, uint32_t& r3) {
    asm volatile("ldmatrix.sync.aligned.m8n8.x4.shared.b16 {%0,%1,%2,%3}, [%4];"
                 : "=r"(r0), "=r"(r1), "=r"(r2), "=r"(r3) : "r"(addr));
}

__device__ __forceinline__ void split2(float a, float b, uint32_t& hi, uint32_t& lo) {
    __nv_bfloat16 ah = __float2bfloat16(a), bh = __float2bfloat16(b);
    __nv_bfloat16 al = __float2bfloat16(a - __bfloat162float(ah));
    __nv_bfloat16 bl = __float2bfloat16(b - __bfloat162float(bh));
    hi = ((uint32_t)__bfloat16_as_ushort(bh) << 16) | __bfloat16_as_ushort(ah);
    lo = ((uint32_t)__bfloat16_as_ushort(bl) << 16) | __bfloat16_as_ushort(al);
}

__device__ __forceinline__ uint32_t hpack(float a, float b) {
    __half2 h = __floats2half2_rn(a, b);
    return *(uint32_t*)&h;
}

__device__ __forceinline__ uint32_t smem_u32(const void* p) {
    uint32_t a;
    asm("{ .reg .u64 t; cvta.to.shared.u64 t, %1; cvt.u32.u64 %0, t; }"
        : "=r"(a) : "l"(p));
    return a;
}

__device__ __forceinline__ void cp_async16(uint32_t smem_dst, const void* gmem_src) {
    asm volatile("cp.async.cg.shared.global [%0], [%1], 16;"
                 :: "r"(smem_dst), "l"(gmem_src));
}
#define CP_COMMIT()  asm volatile("cp.async.commit_group;")
#define CP_WAIT1()   asm volatile("cp.async.wait_group 1;")
#define CP_WAIT0()   asm volatile("cp.async.wait_group 0;")

// Per-lane ldmatrix byte offsets within a tile (stride 72 shorts = 144 B):
//   B: n_off = ((lane>>4)&1)*8 + (lane&7), k_off16 = ((lane>>3)&1)*16 bytes
//   A: m_off = ((lane>>3)&1)*8 + (lane&7), k_off16 = ((lane>>4)&1)*16 bytes
__device__ __forceinline__ uint32_t loff_B(int lane) {
    return (uint32_t)((((lane >> 4) & 1) * 8 + (lane & 7)) * 144 +
                      ((lane >> 3) & 1) * 16);
}
__device__ __forceinline__ uint32_t loff_A(int lane) {
    return (uint32_t)((((lane >> 3) & 1) * 8 + (lane & 7)) * 144 +
                      ((lane >> 4) & 1) * 16);
}

// ---------------------------------------------------------------------------
// Weight prep: w[k][h] -> B[n=h][k] col-major, hi/lo split, stride 72.
// ---------------------------------------------------------------------------
__global__ __launch_bounds__(128) void wprep_kernel(
    const float* __restrict__ wq,
    const float* __restrict__ wk,
    const float* __restrict__ wv)
{
    const int chunk = blockIdx.x;
    const int m3    = blockIdx.y;
    const float* w = (m3 == 0) ? wq : (m3 == 1) ? wk : wv;
    unsigned short* dst_hi = g_wt_hi[m3][chunk];
    unsigned short* dst_lo = g_wt_lo[m3][chunk];
    const int tid = threadIdx.x;

    for (int e = 0; e < 16; e++) {
        int p  = e * 128 + tid;
        int h  = p >> 5;
        int kk = (p & 31) * 2;
        float v0 = w[(size_t)(chunk * 64 + kk)     * H_DIM + h];
        float v1 = w[(size_t)(chunk * 64 + kk + 1) * H_DIM + h];
        uint32_t hp, lp;
        split2(v0, v1, hp, lp);
        *(uint32_t*)&dst_hi[h * WT_STRIDE + kk] = hp;
        *(uint32_t*)&dst_lo[h * WT_STRIDE + kk] = lp;
    }
}

// ---------------------------------------------------------------------------
// Projection via mma.sync, pipelined (R9 structure), fragments via ldmatrix.
// ---------------------------------------------------------------------------
#define PSM_AHI 0
#define PSM_ALO 18432
#define PSM_B   36864
#define PSM_BUF 55296
#define PROJ_SMEM (36864 + 2 * 55296)   // 147456

__global__ __launch_bounds__(384, 1) void proj_mma_kernel(const float* __restrict__ x)
{
    extern __shared__ unsigned char smem[];
    unsigned short* Ah = (unsigned short*)(smem + PSM_AHI);
    unsigned short* Al = (unsigned short*)(smem + PSM_ALO);
    const uint32_t sb = smem_u32(smem);

    const int tid  = threadIdx.x;
    const int wid  = tid >> 5;
    const int lane = tid & 31;
    const int m3   = wid >> 2;
    const int s0   = (wid & 3) * 16;
    const int s1   = s0 + 64;
    const int m0   = blockIdx.x * 128;

    const uint32_t lA = loff_A(lane);
    const uint32_t lB = loff_B(lane);

    float d0[8][4] = {};
    float d1[8][4] = {};
    float2 areg[11];

    {
        for (int p = tid; p < 3456; p += 384) {
            int tile = p / 576;
            int i    = p - tile * 576;
            int tm   = tile >> 1;
            const unsigned short* src = (tile & 1) ? g_wt_lo[tm][0] : g_wt_hi[tm][0];
            cp_async16(sb + PSM_B + tile * 9216 + i * 16, src + i * 8);
        }
        CP_COMMIT();
        #pragma unroll
        for (int e = 0; e < 11; e++) {
            int p = e * 384 + tid;
            if (p < 4096) {
                int r = p >> 5, c = (p & 31) * 2;
                areg[e] = *(const float2*)&x[(size_t)(m0 + r) * C_DIM + c];
            }
        }
    }

    for (int chunk = 0; chunk < 16; chunk++) {
        #pragma unroll
        for (int e = 0; e < 11; e++) {
            int p = e * 384 + tid;
            if (p < 4096) {
                int r = p >> 5, c = (p & 31) * 2;
                uint32_t hp, lp;
                split2(areg[e].x, areg[e].y, hp, lp);
                *(uint32_t*)&Ah[r * WT_STRIDE + c] = hp;
                *(uint32_t*)&Al[r * WT_STRIDE + c] = lp;
            }
        }

        if (chunk < 15) {
            const int kn = (chunk + 1) * 64;
            #pragma unroll
            for (int e = 0; e < 11; e++) {
                int p = e * 384 + tid;
                if (p < 4096) {
                    int r = p >> 5, c = (p & 31) * 2;
                    areg[e] = *(const float2*)&x[(size_t)(m0 + r) * C_DIM + kn + c];
                }
            }
            const uint32_t bufn = sb + PSM_B + ((chunk + 1) & 1) * PSM_BUF;
            for (int p = tid; p < 3456; p += 384) {
                int tile = p / 576;
                int i    = p - tile * 576;
                int tm   = tile >> 1;
                const unsigned short* src = (tile & 1) ? g_wt_lo[tm][chunk + 1]
                                                       : g_wt_hi[tm][chunk + 1];
                cp_async16(bufn + tile * 9216 + i * 16, src + i * 8);
            }
            CP_COMMIT();
            CP_WAIT1();
        } else {
            CP_WAIT0();
        }
        __syncthreads();

        const uint32_t bhB = sb + PSM_B + (chunk & 1) * PSM_BUF + (m3 * 2 + 0) * 9216;
        const uint32_t blB = bhB + 9216;
        const uint32_t ahB = sb + PSM_AHI;
        const uint32_t alB = sb + PSM_ALO;

        #pragma unroll
        for (int ks = 0; ks < 4; ks++) {
            const uint32_t ko = ks * 32;
            uint32_t ah0[4], al0[4], ah1[4], al1[4];
            ldsm_x4(ahB + s0 * 144 + ko + lA, ah0[0], ah0[1], ah0[2], ah0[3]);
            ldsm_x4(alB + s0 * 144 + ko + lA, al0[0], al0[1], al0[2], al0[3]);
            ldsm_x4(ahB + s1 * 144 + ko + lA, ah1[0], ah1[1], ah1[2], ah1[3]);
            ldsm_x4(alB + s1 * 144 + ko + lA, al1[0], al1[1], al1[2], al1[3]);
            #pragma unroll
            for (int j = 0; j < 4; j++) {
                uint32_t bh[4], bl[4];
                ldsm_x4(bhB + j * 2304 + ko + lB, bh[0], bh[1], bh[2], bh[3]);
                ldsm_x4(blB + j * 2304 + ko + lB, bl[0], bl[1], bl[2], bl[3]);
                // nt = 2j
                mma_bf16(d0[2 * j], ah0, bh[0], bh[1]);
                mma_bf16(d0[2 * j], ah0, bl[0], bl[1]);
                mma_bf16(d0[2 * j], al0, bh[0], bh[1]);
                mma_bf16(d1[2 * j], ah1, bh[0], bh[1]);
                mma_bf16(d1[2 * j], ah1, bl[0], bl[1]);
                mma_bf16(d1[2 * j], al1, bh[0], bh[1]);
                // nt = 2j+1
                mma_bf16(d0[2 * j + 1], ah0, bh[2], bh[3]);
                mma_bf16(d0[2 * j + 1], ah0, bl[2], bl[3]);
                mma_bf16(d0[2 * j + 1], al0, bh[2], bh[3]);
                mma_bf16(d1[2 * j + 1], ah1, bh[2], bh[3]);
                mma_bf16(d1[2 * j + 1], ah1, bl[2], bl[3]);
                mma_bf16(d1[2 * j + 1], al1, bh[2], bh[3]);
            }
        }
        __syncthreads();
    }

    const int gg = lane >> 2;
    const int tt = lane & 3;
    #pragma unroll
    for (int sp = 0; sp < 2; sp++) {
        float (*d)[4] = sp ? d1 : d0;
        const int grow0 = m0 + (sp ? s1 : s0) + gg;
        if (m3 == 0) {
            #pragma unroll
            for (int nt = 0; nt < 8; nt++) {
                int col = nt * 8 + tt * 2;
                uint32_t h0, l0, h1, l1;
                split2(d[nt][0] * 0.125f, d[nt][1] * 0.125f, h0, l0);
                split2(d[nt][2] * 0.125f, d[nt][3] * 0.125f, h1, l1);
                *(uint32_t*)&g_qh[(size_t)grow0 * 64 + col] = h0;
                *(uint32_t*)&g_ql[(size_t)grow0 * 64 + col] = l0;
                *(uint32_t*)&g_qh[(size_t)(grow0 + 8) * 64 + col] = h1;
                *(uint32_t*)&g_ql[(size_t)(grow0 + 8) * 64 + col] = l1;
            }
        } else if (m3 == 1) {
            #pragma unroll
            for (int nt = 0; nt < 8; nt++) {
                int col = nt * 8 + tt * 2;
                uint32_t h0, l0, h1, l1;
                split2(d[nt][0], d[nt][1], h0, l0);
                split2(d[nt][2], d[nt][3], h1, l1);
                *(uint32_t*)&g_kh[(size_t)grow0 * 64 + col] = h0;
                *(uint32_t*)&g_kl[(size_t)grow0 * 64 + col] = l0;
                *(uint32_t*)&g_kh[(size_t)(grow0 + 8) * 64 + col] = h1;
                *(uint32_t*)&g_kl[(size_t)(grow0 + 8) * 64 + col] = l1;
            }
        } else {
            #pragma unroll
            for (int nt = 0; nt < 8; nt++) {
                int col = nt * 8 + tt * 2;
                #pragma unroll
                for (int c = 0; c < 4; c++) {
                    int cc = col + (c & 1);
                    int rr = grow0 + (c >> 1) * 8;
                    __half vh = __float2half_rn(d[nt][c]);
                    g_vth[(size_t)cc * M_ROWS + rr] = *(unsigned short*)&vh;
                }
            }
        }
    }
}

// ---------------------------------------------------------------------------
// Flash attention on mma.sync: fp16 PV, cp.async double-buffered staging,
// fragments via ldmatrix. Structure identical to R11 otherwise.
// ---------------------------------------------------------------------------
#define ATT_TILE  4608                 // shorts per sub-tile (64 x 72)
#define ATT_BUF   (3 * ATT_TILE)       // shorts per buffer
#define ATT_SMEM  (2 * ATT_BUF * 2)    // bytes = 55296

__global__ __launch_bounds__(128, 3) void attn_mma_kernel(float* __restrict__ out)
{
    extern __shared__ unsigned short smA[];
    const uint32_t sb = smem_u32(smA);

    const int tid  = threadIdx.x;
    const int warp = tid >> 5;
    const int lane = tid & 31;
    const int g    = lane >> 2;
    const int t    = lane & 3;
    const int b    = blockIdx.y;
    const int qt   = gridDim.x - 1 - blockIdx.x;   // heavy tiles first
    const int q0   = qt * 64;
    const int mrow = warp * 16;
    const size_t mb = (size_t)b * T_SEQ;
    const uint32_t lB = loff_B(lane);

    // ---- Prologue: stage tile j0=0 into buffer 0 ----
    #pragma unroll
    for (int e = 0; e < 12; e++) {
        int p    = e * 128 + tid;
        int tile = p >> 9;
        int i    = p & 511;
        int row  = i >> 3;
        int c8   = i & 7;
        const unsigned short* src;
        if (tile == 0)      src = &g_kh[(mb + row) * 64 + c8 * 8];
        else if (tile == 1) src = &g_kl[(mb + row) * 64 + c8 * 8];
        else                src = &g_vth[(size_t)row * M_ROWS + mb + c8 * 8];
        cp_async16(sb + (tile * ATT_TILE + row * 72 + c8 * 8) * 2, src);
    }
    CP_COMMIT();

    // ---- Q fragments (loop-invariant) ----
    uint32_t qh[4][4], ql[4][4];
    {
        const int r0 = q0 + mrow + g;
        #pragma unroll
        for (int ks = 0; ks < 4; ks++) {
            const size_t o0 = (mb + r0) * 64 + ks * 16 + 2 * t;
            const size_t o1 = o0 + 8 * 64;
            qh[ks][0] = *(const uint32_t*)&g_qh[o0];
            qh[ks][1] = *(const uint32_t*)&g_qh[o1];
            qh[ks][2] = *(const uint32_t*)&g_qh[o0 + 8];
            qh[ks][3] = *(const uint32_t*)&g_qh[o1 + 8];
            ql[ks][0] = *(const uint32_t*)&g_ql[o0];
            ql[ks][1] = *(const uint32_t*)&g_ql[o1];
            ql[ks][2] = *(const uint32_t*)&g_ql[o0 + 8];
            ql[ks][3] = *(const uint32_t*)&g_ql[o1 + 8];
        }
    }

    float o[8][4] = {};
    float m_r[2] = {-1e30f, -1e30f};
    float l_r[2] = {0.0f, 0.0f};

    for (int j0 = 0; j0 <= q0; j0 += 64) {
        const int cur = (j0 >> 6) & 1;

        if (j0 + 64 <= q0) {
            const int jn = j0 + 64;
            const uint32_t bufn = sb + ((cur ^ 1) * ATT_BUF) * 2;
            #pragma unroll
            for (int e = 0; e < 12; e++) {
                int p    = e * 128 + tid;
                int tile = p >> 9;
                int i    = p & 511;
                int row  = i >> 3;
                int c8   = i & 7;
                const unsigned short* src;
                if (tile == 0)      src = &g_kh[(mb + jn + row) * 64 + c8 * 8];
                else if (tile == 1) src = &g_kl[(mb + jn + row) * 64 + c8 * 8];
                else                src = &g_vth[(size_t)row * M_ROWS + mb + jn + c8 * 8];
                cp_async16(bufn + (tile * ATT_TILE + row * 72 + c8 * 8) * 2, src);
            }
            CP_COMMIT();
            CP_WAIT1();
        } else {
            CP_WAIT0();
        }
        __syncthreads();

        const uint32_t khB = sb + (cur * ATT_BUF) * 2;
        const uint32_t klB = khB + ATT_TILE * 2;
        const uint32_t vhB = khB + 2 * ATT_TILE * 2;

        // ---- S = Q K^T (3-term bf16 split, ldmatrix B) ----
        float s[8][4] = {};
        #pragma unroll
        for (int ks = 0; ks < 4; ks++) {
            const uint32_t ko = ks * 32;
            #pragma unroll
            for (int j = 0; j < 4; j++) {
                uint32_t bh[4], bl[4];
                ldsm_x4(khB + j * 2304 + ko + lB, bh[0], bh[1], bh[2], bh[3]);
                ldsm_x4(klB + j * 2304 + ko + lB, bl[0], bl[1], bl[2], bl[3]);
                mma_bf16(s[2 * j],     qh[ks], bh[0], bh[1]);
                mma_bf16(s[2 * j],     qh[ks], bl[0], bl[1]);
                mma_bf16(s[2 * j],     ql[ks], bh[0], bh[1]);
                mma_bf16(s[2 * j + 1], qh[ks], bh[2], bh[3]);
                mma_bf16(s[2 * j + 1], qh[ks], bl[2], bl[3]);
                mma_bf16(s[2 * j + 1], ql[ks], bh[2], bh[3]);
            }
        }

        // ---- Causal mask (diagonal tile only) ----
        if (j0 == q0) {
            #pragma unroll
            for (int nt = 0; nt < 8; nt++) {
                #pragma unroll
                for (int c = 0; c < 4; c++) {
                    int col = nt * 8 + 2 * t + (c & 1);
                    int row = mrow + g + (c >> 1) * 8;
                    if (col > row) s[nt][c] = -1e30f;
                }
            }
        }

        // ---- Online softmax ----
        float mt0 = -1e30f, mt1 = -1e30f;
        #pragma unroll
        for (int nt = 0; nt < 8; nt++) {
            mt0 = fmaxf(mt0, fmaxf(s[nt][0], s[nt][1]));
            mt1 = fmaxf(mt1, fmaxf(s[nt][2], s[nt][3]));
        }
        mt0 = fmaxf(mt0, __shfl_xor_sync(0xffffffffu, mt0, 1));
        mt0 = fmaxf(mt0, __shfl_xor_sync(0xffffffffu, mt0, 2));
        mt1 = fmaxf(mt1, __shfl_xor_sync(0xffffffffu, mt1, 1));
        mt1 = fmaxf(mt1, __shfl_xor_sync(0xffffffffu, mt1, 2));

        float mn0 = fmaxf(m_r[0], mt0);
        float mn1 = fmaxf(m_r[1], mt1);
        float a0 = __expf(m_r[0] - mn0);
        float a1 = __expf(m_r[1] - mn1);
        m_r[0] = mn0; m_r[1] = mn1;

        float rs0 = 0.0f, rs1 = 0.0f;
        #pragma unroll
        for (int nt = 0; nt < 8; nt++) {
            s[nt][0] = __expf(s[nt][0] - mn0);
            s[nt][1] = __expf(s[nt][1] - mn0);
            s[nt][2] = __expf(s[nt][2] - mn1);
            s[nt][3] = __expf(s[nt][3] - mn1);
            rs0 += s[nt][0] + s[nt][1];
            rs1 += s[nt][2] + s[nt][3];
        }
        rs0 += __shfl_xor_sync(0xffffffffu, rs0, 1);
        rs0 += __shfl_xor_sync(0xffffffffu, rs0, 2);
        rs1 += __shfl_xor_sync(0xffffffffu, rs1, 1);
        rs1 += __shfl_xor_sync(0xffffffffu, rs1, 2);
        l_r[0] = l_r[0] * a0 + rs0;
        l_r[1] = l_r[1] * a1 + rs1;

        #pragma unroll
        for (int nt = 0; nt < 8; nt++) {
            o[nt][0] *= a0; o[nt][1] *= a0;
            o[nt][2] *= a1; o[nt][3] *= a1;
        }

        // ---- O += P V  (fp16 MMA, ldmatrix B) ----
        #pragma unroll
        for (int ks = 0; ks < 4; ks++) {
            uint32_t ph[4];
            const int n0 = 2 * ks, n1 = 2 * ks + 1;
            ph[0] = hpack(s[n0][0], s[n0][1]);
            ph[1] = hpack(s[n0][2], s[n0][3]);
            ph[2] = hpack(s[n1][0], s[n1][1]);
            ph[3] = hpack(s[n1][2], s[n1][3]);
            const uint32_t ko = ks * 32;
            #pragma unroll
            for (int j = 0; j < 4; j++) {
                uint32_t bv[4];
                ldsm_x4(vhB + j * 2304 + ko + lB, bv[0], bv[1], bv[2], bv[3]);
                mma_fp16(o[2 * j],     ph, bv[0], bv[1]);
                mma_fp16(o[2 * j + 1], ph, bv[2], bv[3]);
            }
        }
        __syncthreads();   // all reads of cur buffer done before it's re-staged
    }

    // ---- Finalize ----
    const float inv0 = 1.0f / l_r[0];
    const float inv1 = 1.0f / l_r[1];
    const size_t r0 = mb + q0 + mrow + g;
    #pragma unroll
    for (int nt = 0; nt < 8; nt++) {
        const int col = nt * 8 + 2 * t;
        *(float2*)&out[r0 * 64 + col] =
            make_float2(o[nt][0] * inv0, o[nt][1] * inv0);
        *(float2*)&out[(r0 + 8) * 64 + col] =
            make_float2(o[nt][2] * inv1, o[nt][3] * inv1);
    }
}

// ---------------------------------------------------------------------------
extern "C" void kernel_launch(void* const* d_in, const int* in_sizes, int n_in,
                              void* d_out, int out_size)
{
    const float* x  = (const float*)d_in[0];
    const float* wq = (const float*)d_in[1];
    const float* wk = (const float*)d_in[2];
    const float* wv = (const float*)d_in[3];
    float* out = (float*)d_out;

    (void)in_sizes; (void)n_in; (void)out_size;

    cudaFuncSetAttribute(proj_mma_kernel,
                         cudaFuncAttributeMaxDynamicSharedMemorySize, PROJ_SMEM);
    cudaFuncSetAttribute(attn_mma_kernel,
                         cudaFuncAttributeMaxDynamicSharedMemorySize, ATT_SMEM);

    // 1) Prep transposed/split/padded weights (tiny)
    wprep_kernel<<<dim3(16, 3), 128>>>(wq, wk, wv);

    // 2) QKV projection, pipelined mma.sync (BM=128, ldmatrix fragments)
    proj_mma_kernel<<<M_ROWS / 128, 384, PROJ_SMEM>>>(x);

    // 3) Attention: fp16 PV + cp.async double-buffering + ldmatrix
    attn_mma_kernel<<<dim3(T_SEQ / 64, B_DIM), 128, ATT_SMEM>>>(out);
}